// round 12
// baseline (speedup 1.0000x reference)
#include <cuda_runtime.h>
#include <cuda_fp16.h>
#include <cstdint>
#include <math.h>

#define BB   8
#define SS   4096
#define DD   1024
#define DD2  2048
#define CL   64
#define NCH  64
#define EPSV 1e-5f

// ---------------- scratch (device globals) -----------------------------------
__device__ __half g_xh[BB*SS*DD];                   // rmsnorm x fp16
__device__ __half g_wg[BB*DD2*DD];                  // mixed Wg^T (interleaved n) fp16
__device__ __half g_wo[BB*DD*DD];                   // mixed Wo^T fp16
__device__ __half g_hh[BB*SS*DD];                   // scan h fp16
__device__ __half2 g_ab[BB*SS*DD];                  // packed gates (a,b) fp16
__device__ float g_part[BB*64*DD];                  // per-block partial colsums
__device__ float g_probs [BB*3];
__device__ float g_cA[BB*NCH*DD], g_cB[BB*NCH*DD];

__device__ __forceinline__ float sigm(float x) { return 1.0f / (1.0f + __expf(-x)); }

__device__ __forceinline__ uint32_t cvta_smem(const void* p) {
    uint32_t a;
    asm("{ .reg .u64 t; cvta.to.shared.u64 t, %1; cvt.u32.u64 %0, t; }" : "=r"(a) : "l"(p));
    return a;
}

// ---------------- portable tensor-core primitives ------------------------------
__device__ __forceinline__ void mma16816(float* c, const uint32_t* a, const uint32_t* b) {
    asm volatile(
        "mma.sync.aligned.m16n8k16.row.col.f32.f16.f16.f32 "
        "{%0,%1,%2,%3},{%4,%5,%6,%7},{%8,%9},{%0,%1,%2,%3};"
        : "+f"(c[0]), "+f"(c[1]), "+f"(c[2]), "+f"(c[3])
        : "r"(a[0]), "r"(a[1]), "r"(a[2]), "r"(a[3]), "r"(b[0]), "r"(b[1]));
}
__device__ __forceinline__ void ldm4(uint32_t* r, uint32_t a) {
    asm volatile("ldmatrix.sync.aligned.m8n8.x4.shared.b16 {%0,%1,%2,%3}, [%4];"
        : "=r"(r[0]), "=r"(r[1]), "=r"(r[2]), "=r"(r[3]) : "r"(a));
}
#define CPA(s, g) asm volatile("cp.async.cg.shared.global [%0], [%1], 16;" :: "r"(s), "l"(g))
#define CP_COMMIT() asm volatile("cp.async.commit_group;")
#define CP_WAIT0()  asm volatile("cp.async.wait_group 0;")

#define NT 128     // threads per GEMM CTA (4 warps); 4 CTAs per SM

// smem stage (BK=64, 128B rows, XOR-swizzled): A 64x128B | B 128x128B ; 2 stages
#define A_BYTES    8192
#define STAGE_B    24576
#define SMEM_BYTES 49152

// swizzled byte offset within a matrix: row r (128B rows), 16B-chunk cc
#define SWZ(r, cc) ((r) * 128 + (((cc) ^ ((r) & 7)) << 4))

template<int ROWS>
__device__ __forceinline__ void load_mat(uint32_t sdst, const __half* g, int tid) {
#pragma unroll
    for (int it = 0; it < ROWS * 8 / NT; it++) {
        int idx = tid + it * NT;
        int r = idx >> 3, cc = idx & 7;
        CPA(sdst + SWZ(r, cc), g + (size_t)r * DD + cc * 8);
    }
}
__device__ __forceinline__ void load_stage(uint32_t sbuf,
    const __half* A, const __half* B, int k0, int tid) {
    load_mat<64> (sbuf,           A + k0, tid);
    load_mat<128>(sbuf + A_BYTES, B + k0, tid);
}

// 64x128 CTA tile, 4 warps (1M x 4N), warp tile 64x32; fp16, BK=64, 2-stage pipe.
__device__ __forceinline__ void gemm_mainloop(
    float c[4][4][4], uint32_t sb,
    const __half* A, const __half* B, int tid) {

    int lane = tid & 31, wid = tid >> 5;
    int wn = wid;                                        // warp grid 1M x 4N
    int ra = lane & 15;                                  // A row (mf adds 16)
    int rb = wn * 32 + (lane & 7) + ((lane >> 4) << 3);  // B row (ng adds 16)
    int ca0 = lane >> 4;                                 // A chunk base (ks adds 2)
    int cb0 = (lane >> 3) & 1;                           // B chunk base (ks adds 2)

    load_stage(sb, A, B, 0, tid); CP_COMMIT();

#pragma unroll 1
    for (int s = 0; s < 16; s++) {
        CP_WAIT0();
        __syncthreads();
        if (s < 15) {
            load_stage(sb + ((s + 1) & 1) * STAGE_B, A, B, (s + 1) * 64, tid);
            CP_COMMIT();
        }
        uint32_t base  = sb + (s & 1) * STAGE_B;
        uint32_t baseB = base + A_BYTES;
#pragma unroll
        for (int ks = 0; ks < 4; ks++) {
            uint32_t ah[4][4], bh[2][4];
#pragma unroll
            for (int mf = 0; mf < 4; mf++)
                ldm4(ah[mf], base + SWZ(ra + mf * 16, ca0 + ks * 2));
#pragma unroll
            for (int ng = 0; ng < 2; ng++)
                ldm4(bh[ng], baseB + SWZ(rb + ng * 16, cb0 + ks * 2));
#pragma unroll
            for (int mf = 0; mf < 4; mf++)
#pragma unroll
                for (int nf = 0; nf < 4; nf++)
                    mma16816(c[mf][nf], ah[mf], &bh[nf >> 1][(nf & 1) * 2]);
        }
    }
    __syncthreads();
}

// ---------------- rmsnorm -> fp16 + per-block partial colsum ---------------------
__global__ void __launch_bounds__(256) k_rmsnorm(const float* __restrict__ inp,
                                                 const float* __restrict__ normw) {
    int b = blockIdx.y, t = threadIdx.x, warp = t >> 5, lane = t & 31;
    __shared__ float sw[DD];
    __shared__ float scs[DD];
    for (int i = t; i < DD; i += 256) { sw[i] = normw[i]; scs[i] = 0.0f; }
    __syncthreads();
    float csum[32];
#pragma unroll
    for (int k = 0; k < 32; k++) csum[k] = 0.0f;
    int s_base = blockIdx.x * 64;
#pragma unroll 1
    for (int r = 0; r < 8; r++) {
        int s = s_base + warp + r * 8;
        const float* row = inp + (size_t)(b * SS + s) * DD;
        float v[32], ss = 0.0f;
#pragma unroll
        for (int k = 0; k < 32; k++) { v[k] = row[lane + 32 * k]; ss += v[k] * v[k]; }
#pragma unroll
        for (int o = 16; o > 0; o >>= 1) ss += __shfl_xor_sync(0xffffffffu, ss, o);
        float inv = rsqrtf(ss * (1.0f / DD) + EPSV);
        size_t ro = (size_t)(b * SS + s) * DD;
#pragma unroll
        for (int k = 0; k < 32; k++) {
            float xv = v[k] * inv * sw[lane + 32 * k];
            g_xh[ro + lane + 32 * k] = __float2half_rn(xv);
            csum[k] += xv;
        }
    }
#pragma unroll
    for (int k = 0; k < 32; k++) atomicAdd(&scs[lane + 32 * k], csum[k]);
    __syncthreads();
    for (int i = t; i < DD; i += 256)
        g_part[((size_t)b * 64 + blockIdx.x) * DD + i] = scs[i];
}

// ---------------- router (reduces partials) + aux_loss ----------------------------
__global__ void k_router(const float* __restrict__ rw, const float* __restrict__ rb,
                         float* out, int out_size) {
    int b = blockIdx.x, t = threadIdx.x;
    if (b == 0 && t == 0 && out_size >= BB*SS*DD + BB*DD + 1)
        out[BB*SS*DD + BB*DD] = 0.0f;
    float p0 = 0, p1 = 0, p2 = 0;
    for (int d = t; d < DD; d += 128) {
        float cs = 0.0f;
        for (int blk = 0; blk < 64; blk++)
            cs += g_part[((size_t)b * 64 + blk) * DD + d];
        cs *= (1.0f / SS);
        p0 += cs * rw[d * 3 + 0];
        p1 += cs * rw[d * 3 + 1];
        p2 += cs * rw[d * 3 + 2];
    }
    __shared__ float sm[3][128];
    sm[0][t] = p0; sm[1][t] = p1; sm[2][t] = p2;
    __syncthreads();
    for (int o = 64; o > 0; o >>= 1) {
        if (t < o) { sm[0][t] += sm[0][t+o]; sm[1][t] += sm[1][t+o]; sm[2][t] += sm[2][t+o]; }
        __syncthreads();
    }
    if (t == 0) {
        float l0 = sm[0][0] + rb[0], l1 = sm[1][0] + rb[1], l2 = sm[2][0] + rb[2];
        float m = fmaxf(l0, fmaxf(l1, l2));
        float e0 = __expf(l0-m), e1 = __expf(l1-m), e2 = __expf(l2-m);
        float inv = 1.0f / (e0 + e1 + e2);
        g_probs[b*3+0] = e0*inv; g_probs[b*3+1] = e1*inv; g_probs[b*3+2] = e2*inv;
    }
}

// ---------------- mix + transpose Wg (interleaved n) -> fp16; b in fastest dim ---
__global__ void __launch_bounds__(256) k_mixgT(const float* __restrict__ wgh) {
    int b = blockIdx.x & 7;
    int tile = blockIdx.x >> 3;
    int which = blockIdx.y;
    int jt = tile & 31, kt2 = tile >> 5;
    int j0 = jt * 32, k0 = kt2 * 32;
    float p0 = g_probs[b*3+0], p1 = g_probs[b*3+1], p2 = g_probs[b*3+2];
    __shared__ float s[32][33];
    int c = threadIdx.x & 31, r = threadIdx.x >> 5;
#pragma unroll
    for (int rr = 0; rr < 4; rr++) {
        int k = k0 + r + 8 * rr;
        size_t o0 = (size_t)k * DD2 + (size_t)which * DD + j0 + c;
        s[r + 8*rr][c] = p0 * wgh[o0] + p1 * wgh[o0 + (size_t)DD*DD2] + p2 * wgh[o0 + (size_t)2*DD*DD2];
    }
    __syncthreads();
#pragma unroll
    for (int rr = 0; rr < 4; rr++) {
        int jl = r + 8 * rr, kl = c;
        size_t off = ((size_t)b * DD2 + 2*(j0+jl) + which) * DD + k0 + kl;
        g_wg[off] = __float2half_rn(s[kl][jl]);
    }
}

// ---------------- mix + transpose Wo -> fp16; b in fastest dim --------------------
__global__ void __launch_bounds__(256) k_mixoT(const float* __restrict__ wout) {
    int b = blockIdx.x & 7;
    int tile = blockIdx.x >> 3;
    int jt = tile & 31, kt2 = tile >> 5;
    int j0 = jt * 32, k0 = kt2 * 32;
    float p0 = g_probs[b*3+0], p1 = g_probs[b*3+1], p2 = g_probs[b*3+2];
    __shared__ float s[32][33];
    int c = threadIdx.x & 31, r = threadIdx.x >> 5;
#pragma unroll
    for (int rr = 0; rr < 4; rr++) {
        int k = k0 + r + 8 * rr;
        size_t o0 = (size_t)k * DD + j0 + c;
        s[r + 8*rr][c] = p0 * wout[o0] + p1 * wout[o0 + (size_t)DD*DD] + p2 * wout[o0 + (size_t)2*DD*DD];
    }
    __syncthreads();
#pragma unroll
    for (int rr = 0; rr < 4; rr++) {
        int jl = r + 8 * rr, kl = c;
        size_t off = ((size_t)b * DD + j0 + jl) * DD + k0 + kl;
        g_wo[off] = __float2half_rn(s[kl][jl]);
    }
}

// ---------------- GEMM1 (per batch): hg = x @ Wg^T -> (a,b) + fused chunk-scan -----
__global__ void __launch_bounds__(NT, 4) k_gemm1(const float* __restrict__ state, int b) {
    extern __shared__ __align__(128) char smraw[];
    uint32_t sb = cvta_smem(smraw);
    int tid = threadIdx.x;
    int m0 = blockIdx.y * 64, n0 = blockIdx.x * 128;

    const __half* A = g_xh + ((size_t)b * SS  + m0) * DD;
    const __half* B = g_wg + ((size_t)b * DD2 + n0) * DD;

    float c[4][4][4];
#pragma unroll
    for (int i = 0; i < 4; i++)
#pragma unroll
        for (int j = 0; j < 4; j++)
#pragma unroll
            for (int k = 0; k < 4; k++) c[i][j][k] = 0.0f;

    gemm_mainloop(c, sb, A, B, tid);

    // stage packed (a,b) half2 into smem (64 rows x 64 j, pitch 68)
    uint32_t* sab = (uint32_t*)smraw;
    int lane = tid & 31, wid = tid >> 5;
    int wn = wid;
    int rloc = lane >> 2;
    int jloc = wn * 16 + (lane & 3);
#pragma unroll
    for (int mf = 0; mf < 4; mf++)
#pragma unroll
        for (int nf = 0; nf < 4; nf++)
#pragma unroll
            for (int hh2 = 0; hh2 < 2; hh2++) {
                float hid  = c[mf][nf][hh2 * 2];
                float gate = c[mf][nf][hh2 * 2 + 1];
                float z  = sigm(gate);
                float gg = (hid >= 0.0f) ? (hid + 0.5f) : sigm(hid);
                int r = rloc + mf * 16 + hh2 * 8;
                int j = jloc + nf * 4;
                __half2 v = __floats2half2_rn(1.0f - z, z * gg);
                sab[r * 68 + j] = *(uint32_t*)&v;
            }
    __syncthreads();

    // coalesced g_ab write (1024 uint4 over 128 threads)
#pragma unroll
    for (int it = 0; it < 8; it++) {
        int idx = tid + it * NT;
        int row = idx >> 4, seg = idx & 15;
        size_t off = ((size_t)b * SS + m0 + row) * DD + (n0 >> 1) + seg * 4;
        uint4 v = *(uint4*)&sab[row * 68 + seg * 4];
        *(uint4*)&g_ab[off] = v;
    }

    // fused scanA: per-chunk (A,B) carries from smem (1 chunk x 64 d-pairs)
    if (tid < 64) {
        int d = tid;
        int cglob = blockIdx.y;                 // chunk index (tile M == CL)
        int dglob = (n0 >> 1) + d;
        float Ac = 1.0f, Bc = 0.0f;
        const uint32_t* base = sab + d;
#pragma unroll 8
        for (int s = 0; s < CL; s++) {
            __half2 ab = *(const __half2*)&base[s * 68];
            float as = __low2float(ab);
            float bs = __high2float(ab);
            if (cglob == 0 && s == 0) bs += as * state[b * DD + dglob];
            Bc = fmaf(as, Bc, bs);
            Ac *= as;
        }
        int off = (b * NCH + cglob) * DD + dglob;
        g_cA[off] = Ac;
        g_cB[off] = Bc;
    }
}

// ---------------- GEMM2 (per batch): out = h @ Wo^T + inputs -----------------------
__global__ void __launch_bounds__(NT, 4) k_gemm2(const float* __restrict__ inputs,
                                                 float* __restrict__ out, int b) {
    extern __shared__ __align__(128) char smraw[];
    uint32_t sb = cvta_smem(smraw);
    int tid = threadIdx.x;
    int m0 = blockIdx.y * 64, n0 = blockIdx.x * 128;

    const __half* A = g_hh + ((size_t)b * SS + m0) * DD;
    const __half* B = g_wo + ((size_t)b * DD + n0) * DD;

    float c[4][4][4];
#pragma unroll
    for (int i = 0; i < 4; i++)
#pragma unroll
        for (int j = 0; j < 4; j++)
#pragma unroll
            for (int k = 0; k < 4; k++) c[i][j][k] = 0.0f;

    gemm_mainloop(c, sb, A, B, tid);

    int lane = tid & 31, wid = tid >> 5;
    int wn = wid;
    int rbase = m0 + (lane >> 2);
    int cbase = n0 + wn * 32 + (lane & 3) * 2;
#pragma unroll
    for (int mf = 0; mf < 4; mf++)
#pragma unroll
        for (int nf = 0; nf < 4; nf++)
#pragma unroll
            for (int hh2 = 0; hh2 < 2; hh2++) {
                int row = rbase + mf * 16 + hh2 * 8;
                int col = cbase + nf * 8;
                size_t off = ((size_t)b * SS + row) * DD + col;
                float2 iv = *(const float2*)&inputs[off];
                float2 ov;
                ov.x = c[mf][nf][hh2 * 2]     + iv.x;
                ov.y = c[mf][nf][hh2 * 2 + 1] + iv.y;
                *(float2*)&out[off] = ov;
            }
}

// ---------------- scan (B: chunk carries; C: apply + h fp16), per batch -----------
__global__ void k_scanB(int b) {
    int d = blockIdx.x * 256 + threadIdx.x;        // over DD
    float h = 0.0f;
    for (int c = 0; c < NCH; c++) {
        int off = (b * NCH + c) * DD + d;
        float A = g_cA[off], Bc = g_cB[off];
        g_cB[off] = h;
        h = fmaf(A, h, Bc);
    }
}

__global__ void k_scanC(const float* __restrict__ state, float* out, int out_size, int b) {
    int idx = blockIdx.x * 256 + threadIdx.x;      // over NCH*DD
    int d = idx & (DD - 1);
    int c = idx >> 10;
    size_t base = (size_t)(b * SS + c * CL) * DD + d;
    float h = g_cB[b * NCH * DD + idx];
#pragma unroll 8
    for (int s = 0; s < CL; s++) {
        __half2 ab = g_ab[base + (size_t)s * DD];
        float as = __low2float(ab);
        float bs = __high2float(ab);
        if (c == 0 && s == 0) bs += as * state[b * DD + d];
        h = fmaf(as, h, bs);
        g_hh[base + (size_t)s * DD] = __float2half_rn(h);
    }
    if (c == NCH - 1 && out_size >= BB*SS*DD + BB*DD)
        out[BB*SS*DD + b * DD + d] = h;
}

// ---------------- launch ------------------------------------------------------------
extern "C" void kernel_launch(void* const* d_in, const int* in_sizes, int n_in,
                              void* d_out, int out_size) {
    const float* inputs = (const float*)d_in[0];
    const float* state  = (const float*)d_in[1];
    const float* normw  = (const float*)d_in[2];
    const float* rw     = (const float*)d_in[3];
    const float* rb     = (const float*)d_in[4];
    const float* wgh    = (const float*)d_in[5];
    const float* wout   = (const float*)d_in[6];
    float* out = (float*)d_out;

    // one-time host-side setup (streams/events are host resources; device work
    // per call is identical and deterministic)
    static cudaStream_t s1 = nullptr, s2 = nullptr;
    static cudaEvent_t e0, eG1[BB], eJ1, eJ2;
    if (!s1) {
        cudaStreamCreateWithFlags(&s1, cudaStreamNonBlocking);
        cudaStreamCreateWithFlags(&s2, cudaStreamNonBlocking);
        cudaEventCreateWithFlags(&e0, cudaEventDisableTiming);
        for (int b = 0; b < BB; b++) cudaEventCreateWithFlags(&eG1[b], cudaEventDisableTiming);
        cudaEventCreateWithFlags(&eJ1, cudaEventDisableTiming);
        cudaEventCreateWithFlags(&eJ2, cudaEventDisableTiming);
        cudaFuncSetAttribute(k_gemm1, cudaFuncAttributeMaxDynamicSharedMemorySize, SMEM_BYTES);
        cudaFuncSetAttribute(k_gemm2, cudaFuncAttributeMaxDynamicSharedMemorySize, SMEM_BYTES);
    }

    // default stream: rmsnorm + router, then fork
    k_rmsnorm<<<dim3(SS / 64, BB), 256>>>(inputs, normw);
    k_router <<<BB, 128>>>(rw, rb, out, out_size);
    cudaEventRecord(e0, 0);
    cudaStreamWaitEvent(s1, e0, 0);
    cudaStreamWaitEvent(s2, e0, 0);

    // s1: weight mix for gemm1, then per-batch gemm1
    k_mixgT<<<dim3(8192, 2), 256, 0, s1>>>(wgh);
    for (int b = 0; b < BB; b++) {
        k_gemm1<<<dim3(DD2 / 128, SS / 64), NT, SMEM_BYTES, s1>>>(state, b);
        cudaEventRecord(eG1[b], s1);
    }
    cudaEventRecord(eJ1, s1);

    // s2: weight mix for gemm2, then per-batch scan + gemm2 (overlaps later gemm1s)
    k_mixoT<<<dim3(8192, 1), 256, 0, s2>>>(wout);
    for (int b = 0; b < BB; b++) {
        cudaStreamWaitEvent(s2, eG1[b], 0);
        k_scanB<<<DD / 256, 256, 0, s2>>>(b);
        k_scanC<<<(NCH * DD) / 256, 256, 0, s2>>>(state, out, out_size, b);
        k_gemm2<<<dim3(DD / 128, SS / 64), NT, SMEM_BYTES, s2>>>(inputs, out, b);
    }
    cudaEventRecord(eJ2, s2);

    // join back to origin stream
    cudaStreamWaitEvent(0, eJ1, 0);
    cudaStreamWaitEvent(0, eJ2, 0);
}

// round 13
// speedup vs baseline: 1.3153x; 1.3153x over previous
#include <cuda_runtime.h>
#include <cuda_fp16.h>
#include <cstdint>
#include <math.h>

#define BB   8
#define SS   4096
#define DD   1024
#define DD2  2048
#define CL   64
#define NCH  64
#define EPSV 1e-5f

// ---------------- scratch (device globals) -----------------------------------
__device__ __half g_xh[BB*SS*DD];                   // rmsnorm x fp16
__device__ __half g_wg[BB*DD2*DD];                  // mixed Wg^T (interleaved n) fp16
__device__ __half g_wo[BB*DD*DD];                   // mixed Wo^T fp16
__device__ __half g_hh[BB*SS*DD];                   // scan h fp16
__device__ __half2 g_ab[BB*SS*DD];                  // packed gates (a,b) fp16
__device__ float g_part[BB*64*DD];                  // per-block partial colsums
__device__ float g_probs [BB*3];
__device__ float g_cA[BB*NCH*DD], g_cB[BB*NCH*DD];

__device__ __forceinline__ float sigm(float x) { return 1.0f / (1.0f + __expf(-x)); }

__device__ __forceinline__ uint32_t cvta_smem(const void* p) {
    uint32_t a;
    asm("{ .reg .u64 t; cvta.to.shared.u64 t, %1; cvt.u32.u64 %0, t; }" : "=r"(a) : "l"(p));
    return a;
}

// ---------------- portable tensor-core primitives ------------------------------
__device__ __forceinline__ void mma16816(float* c, const uint32_t* a, const uint32_t* b) {
    asm volatile(
        "mma.sync.aligned.m16n8k16.row.col.f32.f16.f16.f32 "
        "{%0,%1,%2,%3},{%4,%5,%6,%7},{%8,%9},{%0,%1,%2,%3};"
        : "+f"(c[0]), "+f"(c[1]), "+f"(c[2]), "+f"(c[3])
        : "r"(a[0]), "r"(a[1]), "r"(a[2]), "r"(a[3]), "r"(b[0]), "r"(b[1]));
}
__device__ __forceinline__ void ldm4(uint32_t* r, uint32_t a) {
    asm volatile("ldmatrix.sync.aligned.m8n8.x4.shared.b16 {%0,%1,%2,%3}, [%4];"
        : "=r"(r[0]), "=r"(r[1]), "=r"(r[2]), "=r"(r[3]) : "r"(a));
}
#define CPA(s, g) asm volatile("cp.async.cg.shared.global [%0], [%1], 16;" :: "r"(s), "l"(g))
#define CP_COMMIT() asm volatile("cp.async.commit_group;")
#define CP_WAIT2()  asm volatile("cp.async.wait_group 2;")
#define CP_WAIT1()  asm volatile("cp.async.wait_group 1;")
#define CP_WAIT0()  asm volatile("cp.async.wait_group 0;")

#define NT 128     // threads per GEMM CTA (4 warps); 4 CTAs per SM

// smem stage (BK=32, 64B rows, XOR-swizzled): A 64x64B | B 128x64B ; 4 stages
#define A_BYTES    4096
#define STAGE_B    12288
#define SMEM_BYTES 49152

// swizzled byte offset: row r (64B rows), 16B-chunk cc in 0..3.
// bijective (r&1, cc^(r>>1&3)) over 8-row groups -> conflict-free ldmatrix + cp.async
#define SWZ32(r, cc) ((r) * 64 + ((((cc) ^ (((r) >> 1) & 3))) << 4))

template<int ROWS>
__device__ __forceinline__ void load_mat(uint32_t sdst, const __half* g, int tid) {
#pragma unroll
    for (int it = 0; it < ROWS * 4 / NT; it++) {
        int idx = tid + it * NT;
        int r = idx >> 2, cc = idx & 3;
        CPA(sdst + SWZ32(r, cc), g + (size_t)r * DD + cc * 8);
    }
}
__device__ __forceinline__ void load_stage(uint32_t sbuf,
    const __half* A, const __half* B, int k0, int tid) {
    load_mat<64> (sbuf,           A + k0, tid);
    load_mat<128>(sbuf + A_BYTES, B + k0, tid);
}

// 64x128 CTA tile, 4 warps (1M x 4N), warp tile 64x32; fp16, BK=32, 4-stage pipe.
__device__ __forceinline__ void gemm_mainloop(
    float c[4][4][4], uint32_t sb,
    const __half* A, const __half* B, int tid) {

    int lane = tid & 31, wid = tid >> 5;
    int wn = wid;                                        // warp grid 1M x 4N
    int ra = lane & 15;                                  // A row (mf adds 16)
    int rb = wn * 32 + (lane & 7) + ((lane >> 4) << 3);  // B row (ng adds 16)
    int ca0 = lane >> 4;                                 // A chunk base (ks adds 2)
    int cb0 = (lane >> 3) & 1;                           // B chunk base (ks adds 2)

    load_stage(sb,               A, B, 0,  tid); CP_COMMIT();
    load_stage(sb + STAGE_B,     A, B, 32, tid); CP_COMMIT();
    load_stage(sb + 2 * STAGE_B, A, B, 64, tid); CP_COMMIT();

#pragma unroll 1
    for (int s = 0; s < 32; s++) {
        if (s < 30) CP_WAIT2();
        else if (s == 30) CP_WAIT1();
        else CP_WAIT0();
        __syncthreads();
        if (s < 29) {
            load_stage(sb + ((s + 3) & 3) * STAGE_B, A, B, (s + 3) * 32, tid);
            CP_COMMIT();
        }
        uint32_t base  = sb + (s & 3) * STAGE_B;
        uint32_t baseB = base + A_BYTES;
#pragma unroll
        for (int ks = 0; ks < 2; ks++) {
            uint32_t ah[4][4], bh[2][4];
#pragma unroll
            for (int mf = 0; mf < 4; mf++)
                ldm4(ah[mf], base + SWZ32(ra + mf * 16, ca0 + ks * 2));
#pragma unroll
            for (int ng = 0; ng < 2; ng++)
                ldm4(bh[ng], baseB + SWZ32(rb + ng * 16, cb0 + ks * 2));
#pragma unroll
            for (int mf = 0; mf < 4; mf++)
#pragma unroll
                for (int nf = 0; nf < 4; nf++)
                    mma16816(c[mf][nf], ah[mf], &bh[nf >> 1][(nf & 1) * 2]);
        }
    }
    __syncthreads();
}

// ---------------- rmsnorm -> fp16 + per-block partial colsum ---------------------
__global__ void __launch_bounds__(256) k_rmsnorm(const float* __restrict__ inp,
                                                 const float* __restrict__ normw) {
    int b = blockIdx.y, t = threadIdx.x, warp = t >> 5, lane = t & 31;
    __shared__ float sw[DD];
    __shared__ float scs[DD];
    for (int i = t; i < DD; i += 256) { sw[i] = normw[i]; scs[i] = 0.0f; }
    __syncthreads();
    float csum[32];
#pragma unroll
    for (int k = 0; k < 32; k++) csum[k] = 0.0f;
    int s_base = blockIdx.x * 64;
#pragma unroll 1
    for (int r = 0; r < 8; r++) {
        int s = s_base + warp + r * 8;
        const float* row = inp + (size_t)(b * SS + s) * DD;
        float v[32], ss = 0.0f;
#pragma unroll
        for (int k = 0; k < 32; k++) { v[k] = row[lane + 32 * k]; ss += v[k] * v[k]; }
#pragma unroll
        for (int o = 16; o > 0; o >>= 1) ss += __shfl_xor_sync(0xffffffffu, ss, o);
        float inv = rsqrtf(ss * (1.0f / DD) + EPSV);
        size_t ro = (size_t)(b * SS + s) * DD;
#pragma unroll
        for (int k = 0; k < 32; k++) {
            float xv = v[k] * inv * sw[lane + 32 * k];
            g_xh[ro + lane + 32 * k] = __float2half_rn(xv);
            csum[k] += xv;
        }
    }
#pragma unroll
    for (int k = 0; k < 32; k++) atomicAdd(&scs[lane + 32 * k], csum[k]);
    __syncthreads();
    for (int i = t; i < DD; i += 256)
        g_part[((size_t)b * 64 + blockIdx.x) * DD + i] = scs[i];
}

// ---------------- router (reduces partials) + aux_loss ----------------------------
__global__ void k_router(const float* __restrict__ rw, const float* __restrict__ rb,
                         float* out, int out_size) {
    int b = blockIdx.x, t = threadIdx.x;
    if (b == 0 && t == 0 && out_size >= BB*SS*DD + BB*DD + 1)
        out[BB*SS*DD + BB*DD] = 0.0f;
    float p0 = 0, p1 = 0, p2 = 0;
    for (int d = t; d < DD; d += 128) {
        float cs = 0.0f;
        for (int blk = 0; blk < 64; blk++)
            cs += g_part[((size_t)b * 64 + blk) * DD + d];
        cs *= (1.0f / SS);
        p0 += cs * rw[d * 3 + 0];
        p1 += cs * rw[d * 3 + 1];
        p2 += cs * rw[d * 3 + 2];
    }
    __shared__ float sm[3][128];
    sm[0][t] = p0; sm[1][t] = p1; sm[2][t] = p2;
    __syncthreads();
    for (int o = 64; o > 0; o >>= 1) {
        if (t < o) { sm[0][t] += sm[0][t+o]; sm[1][t] += sm[1][t+o]; sm[2][t] += sm[2][t+o]; }
        __syncthreads();
    }
    if (t == 0) {
        float l0 = sm[0][0] + rb[0], l1 = sm[1][0] + rb[1], l2 = sm[2][0] + rb[2];
        float m = fmaxf(l0, fmaxf(l1, l2));
        float e0 = __expf(l0-m), e1 = __expf(l1-m), e2 = __expf(l2-m);
        float inv = 1.0f / (e0 + e1 + e2);
        g_probs[b*3+0] = e0*inv; g_probs[b*3+1] = e1*inv; g_probs[b*3+2] = e2*inv;
    }
}

// ---------------- mix + transpose Wg (interleaved n) -> fp16; b in fastest dim ---
__global__ void __launch_bounds__(256) k_mixgT(const float* __restrict__ wgh) {
    int b = blockIdx.x & 7;
    int tile = blockIdx.x >> 3;
    int which = blockIdx.y;
    int jt = tile & 31, kt2 = tile >> 5;
    int j0 = jt * 32, k0 = kt2 * 32;
    float p0 = g_probs[b*3+0], p1 = g_probs[b*3+1], p2 = g_probs[b*3+2];
    __shared__ float s[32][33];
    int c = threadIdx.x & 31, r = threadIdx.x >> 5;
#pragma unroll
    for (int rr = 0; rr < 4; rr++) {
        int k = k0 + r + 8 * rr;
        size_t o0 = (size_t)k * DD2 + (size_t)which * DD + j0 + c;
        s[r + 8*rr][c] = p0 * wgh[o0] + p1 * wgh[o0 + (size_t)DD*DD2] + p2 * wgh[o0 + (size_t)2*DD*DD2];
    }
    __syncthreads();
#pragma unroll
    for (int rr = 0; rr < 4; rr++) {
        int jl = r + 8 * rr, kl = c;
        size_t off = ((size_t)b * DD2 + 2*(j0+jl) + which) * DD + k0 + kl;
        g_wg[off] = __float2half_rn(s[kl][jl]);
    }
}

// ---------------- mix + transpose Wo -> fp16; b in fastest dim --------------------
__global__ void __launch_bounds__(256) k_mixoT(const float* __restrict__ wout) {
    int b = blockIdx.x & 7;
    int tile = blockIdx.x >> 3;
    int jt = tile & 31, kt2 = tile >> 5;
    int j0 = jt * 32, k0 = kt2 * 32;
    float p0 = g_probs[b*3+0], p1 = g_probs[b*3+1], p2 = g_probs[b*3+2];
    __shared__ float s[32][33];
    int c = threadIdx.x & 31, r = threadIdx.x >> 5;
#pragma unroll
    for (int rr = 0; rr < 4; rr++) {
        int k = k0 + r + 8 * rr;
        size_t o0 = (size_t)k * DD + j0 + c;
        s[r + 8*rr][c] = p0 * wout[o0] + p1 * wout[o0 + (size_t)DD*DD] + p2 * wout[o0 + (size_t)2*DD*DD];
    }
    __syncthreads();
#pragma unroll
    for (int rr = 0; rr < 4; rr++) {
        int jl = r + 8 * rr, kl = c;
        size_t off = ((size_t)b * DD + j0 + jl) * DD + k0 + kl;
        g_wo[off] = __float2half_rn(s[kl][jl]);
    }
}

// ---------------- GEMM1: hg = x @ Wg^T -> packed (a,b) + fused chunk-scan ---------
__global__ void __launch_bounds__(NT, 4) k_gemm1(const float* __restrict__ state) {
    extern __shared__ __align__(128) char smraw[];
    uint32_t sb = cvta_smem(smraw);
    int tid = threadIdx.x;
    int b = blockIdx.z, m0 = blockIdx.y * 64, n0 = blockIdx.x * 128;

    const __half* A = g_xh + ((size_t)b * SS  + m0) * DD;
    const __half* B = g_wg + ((size_t)b * DD2 + n0) * DD;

    float c[4][4][4];
#pragma unroll
    for (int i = 0; i < 4; i++)
#pragma unroll
        for (int j = 0; j < 4; j++)
#pragma unroll
            for (int k = 0; k < 4; k++) c[i][j][k] = 0.0f;

    gemm_mainloop(c, sb, A, B, tid);

    // stage packed (a,b) half2 into smem (64 rows x 64 j, pitch 68)
    uint32_t* sab = (uint32_t*)smraw;
    int lane = tid & 31, wid = tid >> 5;
    int wn = wid;
    int rloc = lane >> 2;
    int jloc = wn * 16 + (lane & 3);
#pragma unroll
    for (int mf = 0; mf < 4; mf++)
#pragma unroll
        for (int nf = 0; nf < 4; nf++)
#pragma unroll
            for (int hh2 = 0; hh2 < 2; hh2++) {
                float hid  = c[mf][nf][hh2 * 2];
                float gate = c[mf][nf][hh2 * 2 + 1];
                float z  = sigm(gate);
                float gg = (hid >= 0.0f) ? (hid + 0.5f) : sigm(hid);
                int r = rloc + mf * 16 + hh2 * 8;
                int j = jloc + nf * 4;
                __half2 v = __floats2half2_rn(1.0f - z, z * gg);
                sab[r * 68 + j] = *(uint32_t*)&v;
            }
    __syncthreads();

    // coalesced g_ab write (1024 uint4 over 128 threads)
#pragma unroll
    for (int it = 0; it < 8; it++) {
        int idx = tid + it * NT;
        int row = idx >> 4, seg = idx & 15;
        size_t off = ((size_t)b * SS + m0 + row) * DD + (n0 >> 1) + seg * 4;
        uint4 v = *(uint4*)&sab[row * 68 + seg * 4];
        *(uint4*)&g_ab[off] = v;
    }

    // fused scanA: per-chunk (A,B) carries from smem (1 chunk x 64 d-pairs)
    if (tid < 64) {
        int d = tid;
        int cglob = blockIdx.y;                 // chunk index (tile M == CL)
        int dglob = (n0 >> 1) + d;
        float Ac = 1.0f, Bc = 0.0f;
        const uint32_t* base = sab + d;
#pragma unroll 8
        for (int s = 0; s < CL; s++) {
            __half2 ab = *(const __half2*)&base[s * 68];
            float as = __low2float(ab);
            float bs = __high2float(ab);
            if (cglob == 0 && s == 0) bs += as * state[b * DD + dglob];
            Bc = fmaf(as, Bc, bs);
            Ac *= as;
        }
        int off = (b * NCH + cglob) * DD + dglob;
        g_cA[off] = Ac;
        g_cB[off] = Bc;
    }
}

// ---------------- GEMM2: out = h @ Wo^T + inputs ------------------------------------
__global__ void __launch_bounds__(NT, 4) k_gemm2(const float* __restrict__ inputs,
                                                 float* __restrict__ out) {
    extern __shared__ __align__(128) char smraw[];
    uint32_t sb = cvta_smem(smraw);
    int tid = threadIdx.x;
    int b = blockIdx.z, m0 = blockIdx.y * 64, n0 = blockIdx.x * 128;

    const __half* A = g_hh + ((size_t)b * SS + m0) * DD;
    const __half* B = g_wo + ((size_t)b * DD + n0) * DD;

    float c[4][4][4];
#pragma unroll
    for (int i = 0; i < 4; i++)
#pragma unroll
        for (int j = 0; j < 4; j++)
#pragma unroll
            for (int k = 0; k < 4; k++) c[i][j][k] = 0.0f;

    gemm_mainloop(c, sb, A, B, tid);

    int lane = tid & 31, wid = tid >> 5;
    int wn = wid;
    int rbase = m0 + (lane >> 2);
    int cbase = n0 + wn * 32 + (lane & 3) * 2;
#pragma unroll
    for (int mf = 0; mf < 4; mf++)
#pragma unroll
        for (int nf = 0; nf < 4; nf++)
#pragma unroll
            for (int hh2 = 0; hh2 < 2; hh2++) {
                int row = rbase + mf * 16 + hh2 * 8;
                int col = cbase + nf * 8;
                size_t off = ((size_t)b * SS + row) * DD + col;
                float2 iv = *(const float2*)&inputs[off];
                float2 ov;
                ov.x = c[mf][nf][hh2 * 2]     + iv.x;
                ov.y = c[mf][nf][hh2 * 2 + 1] + iv.y;
                *(float2*)&out[off] = ov;
            }
}

// ---------------- scan (B: chunk carries; C: apply + h fp16) -----------------------
__global__ void k_scanB() {
    int idx = blockIdx.x * 256 + threadIdx.x;
    int d = idx & (DD - 1);
    int b = idx >> 10;
    float h = 0.0f;
    for (int c = 0; c < NCH; c++) {
        int off = (b * NCH + c) * DD + d;
        float A = g_cA[off], Bc = g_cB[off];
        g_cB[off] = h;
        h = fmaf(A, h, Bc);
    }
}

__global__ void k_scanC(const float* __restrict__ state, float* out, int out_size) {
    int idx = blockIdx.x * 256 + threadIdx.x;
    int d = idx & (DD - 1);
    int c = (idx >> 10) & (NCH - 1);
    int b = idx >> 16;
    size_t base = (size_t)(b * SS + c * CL) * DD + d;
    float h = g_cB[idx];
#pragma unroll 8
    for (int s = 0; s < CL; s++) {
        __half2 ab = g_ab[base + (size_t)s * DD];
        float as = __low2float(ab);
        float bs = __high2float(ab);
        if (c == 0 && s == 0) bs += as * state[b * DD + d];
        h = fmaf(as, h, bs);
        g_hh[base + (size_t)s * DD] = __float2half_rn(h);
    }
    if (c == NCH - 1 && out_size >= BB*SS*DD + BB*DD)
        out[BB*SS*DD + b * DD + d] = h;
}

// ---------------- launch ------------------------------------------------------------
extern "C" void kernel_launch(void* const* d_in, const int* in_sizes, int n_in,
                              void* d_out, int out_size) {
    const float* inputs = (const float*)d_in[0];
    const float* state  = (const float*)d_in[1];
    const float* normw  = (const float*)d_in[2];
    const float* rw     = (const float*)d_in[3];
    const float* rb     = (const float*)d_in[4];
    const float* wgh    = (const float*)d_in[5];
    const float* wout   = (const float*)d_in[6];
    float* out = (float*)d_out;

    // one-time host-side setup (host resources only; per-call device work identical)
    static cudaStream_t s2 = nullptr;
    static cudaEvent_t e0, eM;
    if (!s2) {
        cudaStreamCreateWithFlags(&s2, cudaStreamNonBlocking);
        cudaEventCreateWithFlags(&e0, cudaEventDisableTiming);
        cudaEventCreateWithFlags(&eM, cudaEventDisableTiming);
        cudaFuncSetAttribute(k_gemm1, cudaFuncAttributeMaxDynamicSharedMemorySize, SMEM_BYTES);
        cudaFuncSetAttribute(k_gemm2, cudaFuncAttributeMaxDynamicSharedMemorySize, SMEM_BYTES);
    }

    k_rmsnorm<<<dim3(SS / 64, BB), 256>>>(inputs, normw);
    k_router <<<BB, 128>>>(rw, rb, out, out_size);
    cudaEventRecord(e0, 0);

    // s2: mixoT (whole kernel) overlaps gemm1 on the default stream
    cudaStreamWaitEvent(s2, e0, 0);
    k_mixoT<<<dim3(8192, 1), 256, 0, s2>>>(wout);
    cudaEventRecord(eM, s2);

    k_mixgT <<<dim3(8192, 2), 256>>>(wgh);
    k_gemm1 <<<dim3(DD2 / 128, SS / 64, BB), NT, SMEM_BYTES>>>(state);
    k_scanB <<<(BB * DD) / 256, 256>>>();
    k_scanC <<<(BB * NCH * DD) / 256, 256>>>(state, out, out_size);
    cudaStreamWaitEvent(0, eM, 0);
    k_gemm2 <<<dim3(DD / 128, SS / 64, BB), NT, SMEM_BYTES>>>(inputs, out);
}

// round 14
// speedup vs baseline: 1.4228x; 1.0817x over previous
#include <cuda_runtime.h>
#include <cuda_fp16.h>
#include <cstdint>
#include <math.h>

#define BB   8
#define SS   4096
#define DD   1024
#define DD2  2048
#define CL   64
#define NCH  64
#define EPSV 1e-5f

// ---------------- scratch (device globals) -----------------------------------
__device__ __half g_xh[BB*SS*DD];                   // rmsnorm x fp16
__device__ __half g_wg[BB*DD2*DD];                  // mixed Wg^T (interleaved n) fp16
__device__ __half g_wo[BB*DD*DD];                   // mixed Wo^T fp16
__device__ __half g_hh[BB*SS*DD];                   // scan h fp16
__device__ __half2 g_ab[BB*SS*DD];                  // packed gates (a,b) fp16
__device__ float g_part[BB*64*DD];                  // per-block partial colsums
__device__ float g_probs [BB*3];
__device__ float g_cA[BB*NCH*DD], g_cB[BB*NCH*DD];

__device__ __forceinline__ float sigm(float x) { return 1.0f / (1.0f + __expf(-x)); }

__device__ __forceinline__ uint32_t cvta_smem(const void* p) {
    uint32_t a;
    asm("{ .reg .u64 t; cvta.to.shared.u64 t, %1; cvt.u32.u64 %0, t; }" : "=r"(a) : "l"(p));
    return a;
}

// ---------------- portable tensor-core primitives ------------------------------
__device__ __forceinline__ void mma16816(float* c, const uint32_t* a, const uint32_t* b) {
    asm volatile(
        "mma.sync.aligned.m16n8k16.row.col.f32.f16.f16.f32 "
        "{%0,%1,%2,%3},{%4,%5,%6,%7},{%8,%9},{%0,%1,%2,%3};"
        : "+f"(c[0]), "+f"(c[1]), "+f"(c[2]), "+f"(c[3])
        : "r"(a[0]), "r"(a[1]), "r"(a[2]), "r"(a[3]), "r"(b[0]), "r"(b[1]));
}
__device__ __forceinline__ void ldm4(uint32_t* r, uint32_t a) {
    asm volatile("ldmatrix.sync.aligned.m8n8.x4.shared.b16 {%0,%1,%2,%3}, [%4];"
        : "=r"(r[0]), "=r"(r[1]), "=r"(r[2]), "=r"(r[3]) : "r"(a));
}
#define CPA(s, g) asm volatile("cp.async.cg.shared.global [%0], [%1], 16;" :: "r"(s), "l"(g))
#define CP_COMMIT() asm volatile("cp.async.commit_group;")
#define CP_WAIT0()  asm volatile("cp.async.wait_group 0;")

#define NT 128     // threads per GEMM CTA (4 warps); 4 CTAs per SM

// smem stage (BK=64, 128B rows, XOR-swizzled): A 64x128B | B 128x128B ; 2 stages
#define A_BYTES    8192
#define STAGE_B    24576
#define SMEM_BYTES 49152

// swizzled byte offset within a matrix: row r (128B rows), 16B-chunk cc
#define SWZ(r, cc) ((r) * 128 + (((cc) ^ ((r) & 7)) << 4))

template<int ROWS>
__device__ __forceinline__ void load_mat(uint32_t sdst, const __half* g, int tid) {
#pragma unroll
    for (int it = 0; it < ROWS * 8 / NT; it++) {
        int idx = tid + it * NT;
        int r = idx >> 3, cc = idx & 7;
        CPA(sdst + SWZ(r, cc), g + (size_t)r * DD + cc * 8);
    }
}
__device__ __forceinline__ void load_stage(uint32_t sbuf,
    const __half* A, const __half* B, int k0, int tid) {
    load_mat<64> (sbuf,           A + k0, tid);
    load_mat<128>(sbuf + A_BYTES, B + k0, tid);
}

// 64x128 CTA tile, 4 warps (1M x 4N), warp tile 64x32; fp16, BK=64, 2-stage pipe.
__device__ __forceinline__ void gemm_mainloop(
    float c[4][4][4], uint32_t sb,
    const __half* A, const __half* B, int tid) {

    int lane = tid & 31, wid = tid >> 5;
    int wn = wid;                                        // warp grid 1M x 4N
    int ra = lane & 15;                                  // A row (mf adds 16)
    int rb = wn * 32 + (lane & 7) + ((lane >> 4) << 3);  // B row (ng adds 16)
    int ca0 = lane >> 4;                                 // A chunk base (ks adds 2)
    int cb0 = (lane >> 3) & 1;                           // B chunk base (ks adds 2)

    load_stage(sb, A, B, 0, tid); CP_COMMIT();

#pragma unroll 1
    for (int s = 0; s < 16; s++) {
        CP_WAIT0();
        __syncthreads();
        if (s < 15) {
            load_stage(sb + ((s + 1) & 1) * STAGE_B, A, B, (s + 1) * 64, tid);
            CP_COMMIT();
        }
        uint32_t base  = sb + (s & 1) * STAGE_B;
        uint32_t baseB = base + A_BYTES;
#pragma unroll
        for (int ks = 0; ks < 4; ks++) {
            uint32_t ah[4][4], bh[2][4];
#pragma unroll
            for (int mf = 0; mf < 4; mf++)
                ldm4(ah[mf], base + SWZ(ra + mf * 16, ca0 + ks * 2));
#pragma unroll
            for (int ng = 0; ng < 2; ng++)
                ldm4(bh[ng], baseB + SWZ(rb + ng * 16, cb0 + ks * 2));
#pragma unroll
            for (int mf = 0; mf < 4; mf++)
#pragma unroll
                for (int nf = 0; nf < 4; nf++)
                    mma16816(c[mf][nf], ah[mf], &bh[nf >> 1][(nf & 1) * 2]);
        }
    }
    __syncthreads();
}

// ---------------- rmsnorm -> fp16 + per-block partial colsum ---------------------
__global__ void __launch_bounds__(256) k_rmsnorm(const float* __restrict__ inp,
                                                 const float* __restrict__ normw) {
    int b = blockIdx.y, t = threadIdx.x, warp = t >> 5, lane = t & 31;
    __shared__ float sw[DD];
    __shared__ float scs[DD];
    for (int i = t; i < DD; i += 256) { sw[i] = normw[i]; scs[i] = 0.0f; }
    __syncthreads();
    float csum[32];
#pragma unroll
    for (int k = 0; k < 32; k++) csum[k] = 0.0f;
    int s_base = blockIdx.x * 64;
#pragma unroll 1
    for (int r = 0; r < 8; r++) {
        int s = s_base + warp + r * 8;
        const float* row = inp + (size_t)(b * SS + s) * DD;
        float v[32], ss = 0.0f;
#pragma unroll
        for (int k = 0; k < 32; k++) { v[k] = row[lane + 32 * k]; ss += v[k] * v[k]; }
#pragma unroll
        for (int o = 16; o > 0; o >>= 1) ss += __shfl_xor_sync(0xffffffffu, ss, o);
        float inv = rsqrtf(ss * (1.0f / DD) + EPSV);
        size_t ro = (size_t)(b * SS + s) * DD;
#pragma unroll
        for (int k = 0; k < 32; k++) {
            float xv = v[k] * inv * sw[lane + 32 * k];
            g_xh[ro + lane + 32 * k] = __float2half_rn(xv);
            csum[k] += xv;
        }
    }
#pragma unroll
    for (int k = 0; k < 32; k++) atomicAdd(&scs[lane + 32 * k], csum[k]);
    __syncthreads();
    for (int i = t; i < DD; i += 256)
        g_part[((size_t)b * 64 + blockIdx.x) * DD + i] = scs[i];
}

// ---------------- router (reduces partials) + aux_loss ----------------------------
__global__ void k_router(const float* __restrict__ rw, const float* __restrict__ rb,
                         float* out, int out_size) {
    int b = blockIdx.x, t = threadIdx.x;
    if (b == 0 && t == 0 && out_size >= BB*SS*DD + BB*DD + 1)
        out[BB*SS*DD + BB*DD] = 0.0f;
    float p0 = 0, p1 = 0, p2 = 0;
    for (int d = t; d < DD; d += 128) {
        float cs = 0.0f;
        for (int blk = 0; blk < 64; blk++)
            cs += g_part[((size_t)b * 64 + blk) * DD + d];
        cs *= (1.0f / SS);
        p0 += cs * rw[d * 3 + 0];
        p1 += cs * rw[d * 3 + 1];
        p2 += cs * rw[d * 3 + 2];
    }
    __shared__ float sm[3][128];
    sm[0][t] = p0; sm[1][t] = p1; sm[2][t] = p2;
    __syncthreads();
    for (int o = 64; o > 0; o >>= 1) {
        if (t < o) { sm[0][t] += sm[0][t+o]; sm[1][t] += sm[1][t+o]; sm[2][t] += sm[2][t+o]; }
        __syncthreads();
    }
    if (t == 0) {
        float l0 = sm[0][0] + rb[0], l1 = sm[1][0] + rb[1], l2 = sm[2][0] + rb[2];
        float m = fmaxf(l0, fmaxf(l1, l2));
        float e0 = __expf(l0-m), e1 = __expf(l1-m), e2 = __expf(l2-m);
        float inv = 1.0f / (e0 + e1 + e2);
        g_probs[b*3+0] = e0*inv; g_probs[b*3+1] = e1*inv; g_probs[b*3+2] = e2*inv;
    }
}

// ---------------- mix + transpose Wg (interleaved n) -> fp16; b in fastest dim ---
__global__ void __launch_bounds__(256) k_mixgT(const float* __restrict__ wgh) {
    int b = blockIdx.x & 7;
    int tile = blockIdx.x >> 3;
    int which = blockIdx.y;
    int jt = tile & 31, kt2 = tile >> 5;
    int j0 = jt * 32, k0 = kt2 * 32;
    float p0 = g_probs[b*3+0], p1 = g_probs[b*3+1], p2 = g_probs[b*3+2];
    __shared__ float s[32][33];
    int c = threadIdx.x & 31, r = threadIdx.x >> 5;
#pragma unroll
    for (int rr = 0; rr < 4; rr++) {
        int k = k0 + r + 8 * rr;
        size_t o0 = (size_t)k * DD2 + (size_t)which * DD + j0 + c;
        s[r + 8*rr][c] = p0 * wgh[o0] + p1 * wgh[o0 + (size_t)DD*DD2] + p2 * wgh[o0 + (size_t)2*DD*DD2];
    }
    __syncthreads();
#pragma unroll
    for (int rr = 0; rr < 4; rr++) {
        int jl = r + 8 * rr, kl = c;
        size_t off = ((size_t)b * DD2 + 2*(j0+jl) + which) * DD + k0 + kl;
        g_wg[off] = __float2half_rn(s[kl][jl]);
    }
}

// ---------------- mix + transpose Wo -> fp16; b in fastest dim --------------------
__global__ void __launch_bounds__(256) k_mixoT(const float* __restrict__ wout) {
    int b = blockIdx.x & 7;
    int tile = blockIdx.x >> 3;
    int jt = tile & 31, kt2 = tile >> 5;
    int j0 = jt * 32, k0 = kt2 * 32;
    float p0 = g_probs[b*3+0], p1 = g_probs[b*3+1], p2 = g_probs[b*3+2];
    __shared__ float s[32][33];
    int c = threadIdx.x & 31, r = threadIdx.x >> 5;
#pragma unroll
    for (int rr = 0; rr < 4; rr++) {
        int k = k0 + r + 8 * rr;
        size_t o0 = (size_t)k * DD + j0 + c;
        s[r + 8*rr][c] = p0 * wout[o0] + p1 * wout[o0 + (size_t)DD*DD] + p2 * wout[o0 + (size_t)2*DD*DD];
    }
    __syncthreads();
#pragma unroll
    for (int rr = 0; rr < 4; rr++) {
        int jl = r + 8 * rr, kl = c;
        size_t off = ((size_t)b * DD + j0 + jl) * DD + k0 + kl;
        g_wo[off] = __float2half_rn(s[kl][jl]);
    }
}

// ---------------- GEMM1: hg = x @ Wg^T -> packed (a,b) + fused chunk-scan ---------
__global__ void __launch_bounds__(NT, 4) k_gemm1(const float* __restrict__ state) {
    extern __shared__ __align__(128) char smraw[];
    uint32_t sb = cvta_smem(smraw);
    int tid = threadIdx.x;
    int b = blockIdx.z, m0 = blockIdx.y * 64, n0 = blockIdx.x * 128;

    const __half* A = g_xh + ((size_t)b * SS  + m0) * DD;
    const __half* B = g_wg + ((size_t)b * DD2 + n0) * DD;

    float c[4][4][4];
#pragma unroll
    for (int i = 0; i < 4; i++)
#pragma unroll
        for (int j = 0; j < 4; j++)
#pragma unroll
            for (int k = 0; k < 4; k++) c[i][j][k] = 0.0f;

    gemm_mainloop(c, sb, A, B, tid);

    // stage packed (a,b) half2 into smem (64 rows x 64 j, pitch 68)
    uint32_t* sab = (uint32_t*)smraw;
    int lane = tid & 31, wid = tid >> 5;
    int wn = wid;
    int rloc = lane >> 2;
    int jloc = wn * 16 + (lane & 3);
#pragma unroll
    for (int mf = 0; mf < 4; mf++)
#pragma unroll
        for (int nf = 0; nf < 4; nf++)
#pragma unroll
            for (int hh2 = 0; hh2 < 2; hh2++) {
                float hid  = c[mf][nf][hh2 * 2];
                float gate = c[mf][nf][hh2 * 2 + 1];
                float z  = sigm(gate);
                float gg = (hid >= 0.0f) ? (hid + 0.5f) : sigm(hid);
                int r = rloc + mf * 16 + hh2 * 8;
                int j = jloc + nf * 4;
                __half2 v = __floats2half2_rn(1.0f - z, z * gg);
                sab[r * 68 + j] = *(uint32_t*)&v;
            }
    __syncthreads();

    // coalesced g_ab write (1024 uint4 over 128 threads)
#pragma unroll
    for (int it = 0; it < 8; it++) {
        int idx = tid + it * NT;
        int row = idx >> 4, seg = idx & 15;
        size_t off = ((size_t)b * SS + m0 + row) * DD + (n0 >> 1) + seg * 4;
        uint4 v = *(uint4*)&sab[row * 68 + seg * 4];
        *(uint4*)&g_ab[off] = v;
    }

    // fused scanA: per-chunk (A,B) carries from smem (1 chunk x 64 d-pairs)
    if (tid < 64) {
        int d = tid;
        int cglob = blockIdx.y;                 // chunk index (tile M == CL)
        int dglob = (n0 >> 1) + d;
        float Ac = 1.0f, Bc = 0.0f;
        const uint32_t* base = sab + d;
#pragma unroll 8
        for (int s = 0; s < CL; s++) {
            __half2 ab = *(const __half2*)&base[s * 68];
            float as = __low2float(ab);
            float bs = __high2float(ab);
            if (cglob == 0 && s == 0) bs += as * state[b * DD + dglob];
            Bc = fmaf(as, Bc, bs);
            Ac *= as;
        }
        int off = (b * NCH + cglob) * DD + dglob;
        g_cA[off] = Ac;
        g_cB[off] = Bc;
    }
}

// ---------------- GEMM2: out = h @ Wo^T + inputs ------------------------------------
__global__ void __launch_bounds__(NT, 4) k_gemm2(const float* __restrict__ inputs,
                                                 float* __restrict__ out) {
    extern __shared__ __align__(128) char smraw[];
    uint32_t sb = cvta_smem(smraw);
    int tid = threadIdx.x;
    int b = blockIdx.z, m0 = blockIdx.y * 64, n0 = blockIdx.x * 128;

    const __half* A = g_hh + ((size_t)b * SS + m0) * DD;
    const __half* B = g_wo + ((size_t)b * DD + n0) * DD;

    float c[4][4][4];
#pragma unroll
    for (int i = 0; i < 4; i++)
#pragma unroll
        for (int j = 0; j < 4; j++)
#pragma unroll
            for (int k = 0; k < 4; k++) c[i][j][k] = 0.0f;

    gemm_mainloop(c, sb, A, B, tid);

    int lane = tid & 31, wid = tid >> 5;
    int wn = wid;
    int rbase = m0 + (lane >> 2);
    int cbase = n0 + wn * 32 + (lane & 3) * 2;
#pragma unroll
    for (int mf = 0; mf < 4; mf++)
#pragma unroll
        for (int nf = 0; nf < 4; nf++)
#pragma unroll
            for (int hh2 = 0; hh2 < 2; hh2++) {
                int row = rbase + mf * 16 + hh2 * 8;
                int col = cbase + nf * 8;
                size_t off = ((size_t)b * SS + row) * DD + col;
                float2 iv = *(const float2*)&inputs[off];
                float2 ov;
                ov.x = c[mf][nf][hh2 * 2]     + iv.x;
                ov.y = c[mf][nf][hh2 * 2 + 1] + iv.y;
                *(float2*)&out[off] = ov;
            }
}

// ---------------- scan (B: chunk carries; C: apply + h fp16) -----------------------
__global__ void k_scanB() {
    int idx = blockIdx.x * 256 + threadIdx.x;
    int d = idx & (DD - 1);
    int b = idx >> 10;
    float h = 0.0f;
    for (int c = 0; c < NCH; c++) {
        int off = (b * NCH + c) * DD + d;
        float A = g_cA[off], Bc = g_cB[off];
        g_cB[off] = h;
        h = fmaf(A, h, Bc);
    }
}

__global__ void k_scanC(const float* __restrict__ state, float* out, int out_size) {
    int idx = blockIdx.x * 256 + threadIdx.x;
    int d = idx & (DD - 1);
    int c = (idx >> 10) & (NCH - 1);
    int b = idx >> 16;
    size_t base = (size_t)(b * SS + c * CL) * DD + d;
    float h = g_cB[idx];
#pragma unroll 8
    for (int s = 0; s < CL; s++) {
        __half2 ab = g_ab[base + (size_t)s * DD];
        float as = __low2float(ab);
        float bs = __high2float(ab);
        if (c == 0 && s == 0) bs += as * state[b * DD + d];
        h = fmaf(as, h, bs);
        g_hh[base + (size_t)s * DD] = __float2half_rn(h);
    }
    if (c == NCH - 1 && out_size >= BB*SS*DD + BB*DD)
        out[BB*SS*DD + b * DD + d] = h;
}

// ---------------- launch ------------------------------------------------------------
extern "C" void kernel_launch(void* const* d_in, const int* in_sizes, int n_in,
                              void* d_out, int out_size) {
    const float* inputs = (const float*)d_in[0];
    const float* state  = (const float*)d_in[1];
    const float* normw  = (const float*)d_in[2];
    const float* rw     = (const float*)d_in[3];
    const float* rb     = (const float*)d_in[4];
    const float* wgh    = (const float*)d_in[5];
    const float* wout   = (const float*)d_in[6];
    float* out = (float*)d_out;

    // one-time host-side setup (host resources only; per-call device work identical)
    static cudaStream_t s2 = nullptr;
    static cudaEvent_t e0, eM;
    if (!s2) {
        cudaStreamCreateWithFlags(&s2, cudaStreamNonBlocking);
        cudaEventCreateWithFlags(&e0, cudaEventDisableTiming);
        cudaEventCreateWithFlags(&eM, cudaEventDisableTiming);
        cudaFuncSetAttribute(k_gemm1, cudaFuncAttributeMaxDynamicSharedMemorySize, SMEM_BYTES);
        cudaFuncSetAttribute(k_gemm2, cudaFuncAttributeMaxDynamicSharedMemorySize, SMEM_BYTES);
    }

    k_rmsnorm<<<dim3(SS / 64, BB), 256>>>(inputs, normw);
    k_router <<<BB, 128>>>(rw, rb, out, out_size);
    cudaEventRecord(e0, 0);

    // s2: mixoT (whole kernel) overlaps gemm1 on the default stream
    cudaStreamWaitEvent(s2, e0, 0);
    k_mixoT<<<dim3(8192, 1), 256, 0, s2>>>(wout);
    cudaEventRecord(eM, s2);

    k_mixgT <<<dim3(8192, 2), 256>>>(wgh);
    k_gemm1 <<<dim3(DD2 / 128, SS / 64, BB), NT, SMEM_BYTES>>>(state);
    k_scanB <<<(BB * DD) / 256, 256>>>();
    k_scanC <<<(BB * NCH * DD) / 256, 256>>>(state, out, out_size);
    cudaStreamWaitEvent(0, eM, 0);
    k_gemm2 <<<dim3(DD / 128, SS / 64, BB), NT, SMEM_BYTES>>>(inputs, out);
}

// round 15
// speedup vs baseline: 1.4829x; 1.0422x over previous
#include <cuda_runtime.h>
#include <cuda_fp16.h>
#include <cstdint>
#include <math.h>

#define BB   8
#define SS   4096
#define DD   1024
#define DD2  2048
#define CL   64
#define NCH  64
#define EPSV 1e-5f

// ---------------- scratch (device globals) -----------------------------------
__device__ __half g_xh[BB*SS*DD];                   // rmsnorm x fp16
__device__ __half g_wg[BB*DD2*DD];                  // mixed Wg^T (interleaved n) fp16
__device__ __half g_wo[BB*DD*DD];                   // mixed Wo^T fp16
__device__ __half g_hh[BB*SS*DD];                   // scan h fp16
__device__ __half2 g_ab[BB*SS*DD];                  // packed gates (a,b) fp16
__device__ float g_part[BB*64*DD];                  // per-block partial colsums
__device__ float g_probs [BB*3];
__device__ float g_cA[BB*NCH*DD], g_cB[BB*NCH*DD];

__device__ __forceinline__ float sigm(float x) { return 1.0f / (1.0f + __expf(-x)); }

__device__ __forceinline__ uint32_t cvta_smem(const void* p) {
    uint32_t a;
    asm("{ .reg .u64 t; cvta.to.shared.u64 t, %1; cvt.u32.u64 %0, t; }" : "=r"(a) : "l"(p));
    return a;
}

// ---------------- portable tensor-core primitives ------------------------------
__device__ __forceinline__ void mma16816(float* c, const uint32_t* a, const uint32_t* b) {
    asm volatile(
        "mma.sync.aligned.m16n8k16.row.col.f32.f16.f16.f32 "
        "{%0,%1,%2,%3},{%4,%5,%6,%7},{%8,%9},{%0,%1,%2,%3};"
        : "+f"(c[0]), "+f"(c[1]), "+f"(c[2]), "+f"(c[3])
        : "r"(a[0]), "r"(a[1]), "r"(a[2]), "r"(a[3]), "r"(b[0]), "r"(b[1]));
}
__device__ __forceinline__ void ldm4(uint32_t* r, uint32_t a) {
    asm volatile("ldmatrix.sync.aligned.m8n8.x4.shared.b16 {%0,%1,%2,%3}, [%4];"
        : "=r"(r[0]), "=r"(r[1]), "=r"(r[2]), "=r"(r[3]) : "r"(a));
}
#define CPA(s, g) asm volatile("cp.async.cg.shared.global [%0], [%1], 16;" :: "r"(s), "l"(g))
#define CP_COMMIT() asm volatile("cp.async.commit_group;")
#define CP_WAIT0()  asm volatile("cp.async.wait_group 0;")

#define NT 128     // threads per GEMM CTA (4 warps); 4 CTAs per SM

// smem stage (BK=64, 128B rows, XOR-swizzled): A 64x128B | B 128x128B ; 2 stages
#define A_BYTES    8192
#define STAGE_B    24576
#define SMEM_BYTES 49152

// swizzled byte offset within a matrix: row r (128B rows), 16B-chunk cc
#define SWZ(r, cc) ((r) * 128 + (((cc) ^ ((r) & 7)) << 4))

template<int ROWS>
__device__ __forceinline__ void load_mat(uint32_t sdst, const __half* g, int tid) {
#pragma unroll
    for (int it = 0; it < ROWS * 8 / NT; it++) {
        int idx = tid + it * NT;
        int r = idx >> 3, cc = idx & 7;
        CPA(sdst + SWZ(r, cc), g + (size_t)r * DD + cc * 8);
    }
}
__device__ __forceinline__ void load_stage(uint32_t sbuf,
    const __half* A, const __half* B, int k0, int tid) {
    load_mat<64> (sbuf,           A + k0, tid);
    load_mat<128>(sbuf + A_BYTES, B + k0, tid);
}

// 64x128 CTA tile, 4 warps (1M x 4N), warp tile 64x32; fp16, BK=64, 2-stage pipe.
__device__ __forceinline__ void gemm_mainloop(
    float c[4][4][4], uint32_t sb,
    const __half* A, const __half* B, int tid) {

    int lane = tid & 31, wid = tid >> 5;
    int wn = wid;                                        // warp grid 1M x 4N
    int ra = lane & 15;                                  // A row (mf adds 16)
    int rb = wn * 32 + (lane & 7) + ((lane >> 4) << 3);  // B row (ng adds 16)
    int ca0 = lane >> 4;                                 // A chunk base (ks adds 2)
    int cb0 = (lane >> 3) & 1;                           // B chunk base (ks adds 2)

    load_stage(sb, A, B, 0, tid); CP_COMMIT();

#pragma unroll 1
    for (int s = 0; s < 16; s++) {
        CP_WAIT0();
        __syncthreads();
        if (s < 15) {
            load_stage(sb + ((s + 1) & 1) * STAGE_B, A, B, (s + 1) * 64, tid);
            CP_COMMIT();
        }
        uint32_t base  = sb + (s & 1) * STAGE_B;
        uint32_t baseB = base + A_BYTES;
#pragma unroll
        for (int ks = 0; ks < 4; ks++) {
            uint32_t ah[4][4], bh[2][4];
#pragma unroll
            for (int mf = 0; mf < 4; mf++)
                ldm4(ah[mf], base + SWZ(ra + mf * 16, ca0 + ks * 2));
#pragma unroll
            for (int ng = 0; ng < 2; ng++)
                ldm4(bh[ng], baseB + SWZ(rb + ng * 16, cb0 + ks * 2));
#pragma unroll
            for (int mf = 0; mf < 4; mf++)
#pragma unroll
                for (int nf = 0; nf < 4; nf++)
                    mma16816(c[mf][nf], ah[mf], &bh[nf >> 1][(nf & 1) * 2]);
        }
    }
    __syncthreads();
}

// ---------------- rmsnorm (float4 vectorized) -> fp16 + partial colsum ------------
__global__ void __launch_bounds__(256) k_rmsnorm(const float* __restrict__ inp,
                                                 const float* __restrict__ normw) {
    int b = blockIdx.y, t = threadIdx.x, warp = t >> 5, lane = t & 31;
    __shared__ float sw[DD];
    __shared__ float scs[DD];
    for (int i = t; i < DD; i += 256) { sw[i] = normw[i]; scs[i] = 0.0f; }
    __syncthreads();

    float csum[8][4];
#pragma unroll
    for (int q = 0; q < 8; q++)
#pragma unroll
        for (int j = 0; j < 4; j++) csum[q][j] = 0.0f;

    int s_base = blockIdx.x * 64;
#pragma unroll 1
    for (int r = 0; r < 8; r++) {
        int s = s_base + warp + r * 8;
        const float4* row4 = (const float4*)(inp + (size_t)(b * SS + s) * DD);
        float4 v[8];
        float ss = 0.0f;
#pragma unroll
        for (int q = 0; q < 8; q++) {
            v[q] = row4[lane + 32 * q];
            ss += v[q].x * v[q].x + v[q].y * v[q].y + v[q].z * v[q].z + v[q].w * v[q].w;
        }
#pragma unroll
        for (int o = 16; o > 0; o >>= 1) ss += __shfl_xor_sync(0xffffffffu, ss, o);
        float inv = rsqrtf(ss * (1.0f / DD) + EPSV);
        uint2* xr = (uint2*)(g_xh + (size_t)(b * SS + s) * DD);
#pragma unroll
        for (int q = 0; q < 8; q++) {
            int col0 = (lane + 32 * q) * 4;
            float x0 = v[q].x * inv * sw[col0 + 0];
            float x1 = v[q].y * inv * sw[col0 + 1];
            float x2 = v[q].z * inv * sw[col0 + 2];
            float x3 = v[q].w * inv * sw[col0 + 3];
            __half2 h01 = __floats2half2_rn(x0, x1);
            __half2 h23 = __floats2half2_rn(x2, x3);
            uint2 pack;
            pack.x = *(uint32_t*)&h01;
            pack.y = *(uint32_t*)&h23;
            xr[lane + 32 * q] = pack;
            csum[q][0] += x0; csum[q][1] += x1; csum[q][2] += x2; csum[q][3] += x3;
        }
    }
#pragma unroll
    for (int q = 0; q < 8; q++) {
        int col0 = (lane + 32 * q) * 4;
#pragma unroll
        for (int j = 0; j < 4; j++) atomicAdd(&scs[col0 + j], csum[q][j]);
    }
    __syncthreads();
    for (int i = t; i < DD; i += 256)
        g_part[((size_t)b * 64 + blockIdx.x) * DD + i] = scs[i];
}

// ---------------- router (reduces partials) + aux_loss ----------------------------
__global__ void k_router(const float* __restrict__ rw, const float* __restrict__ rb,
                         float* out, int out_size) {
    int b = blockIdx.x, t = threadIdx.x;
    if (b == 0 && t == 0 && out_size >= BB*SS*DD + BB*DD + 1)
        out[BB*SS*DD + BB*DD] = 0.0f;
    float p0 = 0, p1 = 0, p2 = 0;
    for (int d = t; d < DD; d += 128) {
        float cs = 0.0f;
        for (int blk = 0; blk < 64; blk++)
            cs += g_part[((size_t)b * 64 + blk) * DD + d];
        cs *= (1.0f / SS);
        p0 += cs * rw[d * 3 + 0];
        p1 += cs * rw[d * 3 + 1];
        p2 += cs * rw[d * 3 + 2];
    }
    __shared__ float sm[3][128];
    sm[0][t] = p0; sm[1][t] = p1; sm[2][t] = p2;
    __syncthreads();
    for (int o = 64; o > 0; o >>= 1) {
        if (t < o) { sm[0][t] += sm[0][t+o]; sm[1][t] += sm[1][t+o]; sm[2][t] += sm[2][t+o]; }
        __syncthreads();
    }
    if (t == 0) {
        float l0 = sm[0][0] + rb[0], l1 = sm[1][0] + rb[1], l2 = sm[2][0] + rb[2];
        float m = fmaxf(l0, fmaxf(l1, l2));
        float e0 = __expf(l0-m), e1 = __expf(l1-m), e2 = __expf(l2-m);
        float inv = 1.0f / (e0 + e1 + e2);
        g_probs[b*3+0] = e0*inv; g_probs[b*3+1] = e1*inv; g_probs[b*3+2] = e2*inv;
    }
}

// ---------------- mix + transpose Wg (interleaved n) -> fp16; b in fastest dim ---
__global__ void __launch_bounds__(256) k_mixgT(const float* __restrict__ wgh) {
    int b = blockIdx.x & 7;
    int tile = blockIdx.x >> 3;
    int which = blockIdx.y;
    int jt = tile & 31, kt2 = tile >> 5;
    int j0 = jt * 32, k0 = kt2 * 32;
    float p0 = g_probs[b*3+0], p1 = g_probs[b*3+1], p2 = g_probs[b*3+2];
    __shared__ float s[32][33];
    int c = threadIdx.x & 31, r = threadIdx.x >> 5;
#pragma unroll
    for (int rr = 0; rr < 4; rr++) {
        int k = k0 + r + 8 * rr;
        size_t o0 = (size_t)k * DD2 + (size_t)which * DD + j0 + c;
        s[r + 8*rr][c] = p0 * wgh[o0] + p1 * wgh[o0 + (size_t)DD*DD2] + p2 * wgh[o0 + (size_t)2*DD*DD2];
    }
    __syncthreads();
#pragma unroll
    for (int rr = 0; rr < 4; rr++) {
        int jl = r + 8 * rr, kl = c;
        size_t off = ((size_t)b * DD2 + 2*(j0+jl) + which) * DD + k0 + kl;
        g_wg[off] = __float2half_rn(s[kl][jl]);
    }
}

// ---------------- mix + transpose Wo -> fp16; b in fastest dim --------------------
__global__ void __launch_bounds__(256) k_mixoT(const float* __restrict__ wout) {
    int b = blockIdx.x & 7;
    int tile = blockIdx.x >> 3;
    int jt = tile & 31, kt2 = tile >> 5;
    int j0 = jt * 32, k0 = kt2 * 32;
    float p0 = g_probs[b*3+0], p1 = g_probs[b*3+1], p2 = g_probs[b*3+2];
    __shared__ float s[32][33];
    int c = threadIdx.x & 31, r = threadIdx.x >> 5;
#pragma unroll
    for (int rr = 0; rr < 4; rr++) {
        int k = k0 + r + 8 * rr;
        size_t o0 = (size_t)k * DD + j0 + c;
        s[r + 8*rr][c] = p0 * wout[o0] + p1 * wout[o0 + (size_t)DD*DD] + p2 * wout[o0 + (size_t)2*DD*DD];
    }
    __syncthreads();
#pragma unroll
    for (int rr = 0; rr < 4; rr++) {
        int jl = r + 8 * rr, kl = c;
        size_t off = ((size_t)b * DD + j0 + jl) * DD + k0 + kl;
        g_wo[off] = __float2half_rn(s[kl][jl]);
    }
}

// ---------------- GEMM1: hg = x @ Wg^T -> packed (a,b) + fused chunk-scan ---------
__global__ void __launch_bounds__(NT, 4) k_gemm1(const float* __restrict__ state) {
    extern __shared__ __align__(128) char smraw[];
    uint32_t sb = cvta_smem(smraw);
    int tid = threadIdx.x;
    int b = blockIdx.z, m0 = blockIdx.y * 64, n0 = blockIdx.x * 128;

    const __half* A = g_xh + ((size_t)b * SS  + m0) * DD;
    const __half* B = g_wg + ((size_t)b * DD2 + n0) * DD;

    float c[4][4][4];
#pragma unroll
    for (int i = 0; i < 4; i++)
#pragma unroll
        for (int j = 0; j < 4; j++)
#pragma unroll
            for (int k = 0; k < 4; k++) c[i][j][k] = 0.0f;

    gemm_mainloop(c, sb, A, B, tid);

    // stage packed (a,b) half2 into smem (64 rows x 64 j, pitch 68)
    uint32_t* sab = (uint32_t*)smraw;
    int lane = tid & 31, wid = tid >> 5;
    int wn = wid;
    int rloc = lane >> 2;
    int jloc = wn * 16 + (lane & 3);
#pragma unroll
    for (int mf = 0; mf < 4; mf++)
#pragma unroll
        for (int nf = 0; nf < 4; nf++)
#pragma unroll
            for (int hh2 = 0; hh2 < 2; hh2++) {
                float hid  = c[mf][nf][hh2 * 2];
                float gate = c[mf][nf][hh2 * 2 + 1];
                float z  = sigm(gate);
                float gg = (hid >= 0.0f) ? (hid + 0.5f) : sigm(hid);
                int r = rloc + mf * 16 + hh2 * 8;
                int j = jloc + nf * 4;
                __half2 v = __floats2half2_rn(1.0f - z, z * gg);
                sab[r * 68 + j] = *(uint32_t*)&v;
            }
    __syncthreads();

    // coalesced g_ab write (1024 uint4 over 128 threads)
#pragma unroll
    for (int it = 0; it < 8; it++) {
        int idx = tid + it * NT;
        int row = idx >> 4, seg = idx & 15;
        size_t off = ((size_t)b * SS + m0 + row) * DD + (n0 >> 1) + seg * 4;
        uint4 v = *(uint4*)&sab[row * 68 + seg * 4];
        *(uint4*)&g_ab[off] = v;
    }

    // fused scanA: per-chunk (A,B) carries from smem (1 chunk x 64 d-pairs)
    if (tid < 64) {
        int d = tid;
        int cglob = blockIdx.y;                 // chunk index (tile M == CL)
        int dglob = (n0 >> 1) + d;
        float Ac = 1.0f, Bc = 0.0f;
        const uint32_t* base = sab + d;
#pragma unroll 8
        for (int s = 0; s < CL; s++) {
            __half2 ab = *(const __half2*)&base[s * 68];
            float as = __low2float(ab);
            float bs = __high2float(ab);
            if (cglob == 0 && s == 0) bs += as * state[b * DD + dglob];
            Bc = fmaf(as, Bc, bs);
            Ac *= as;
        }
        int off = (b * NCH + cglob) * DD + dglob;
        g_cA[off] = Ac;
        g_cB[off] = Bc;
    }
}

// ---------------- GEMM2: out = h @ Wo^T + inputs ------------------------------------
__global__ void __launch_bounds__(NT, 4) k_gemm2(const float* __restrict__ inputs,
                                                 float* __restrict__ out) {
    extern __shared__ __align__(128) char smraw[];
    uint32_t sb = cvta_smem(smraw);
    int tid = threadIdx.x;
    int b = blockIdx.z, m0 = blockIdx.y * 64, n0 = blockIdx.x * 128;

    const __half* A = g_hh + ((size_t)b * SS + m0) * DD;
    const __half* B = g_wo + ((size_t)b * DD + n0) * DD;

    float c[4][4][4];
#pragma unroll
    for (int i = 0; i < 4; i++)
#pragma unroll
        for (int j = 0; j < 4; j++)
#pragma unroll
            for (int k = 0; k < 4; k++) c[i][j][k] = 0.0f;

    gemm_mainloop(c, sb, A, B, tid);

    int lane = tid & 31, wid = tid >> 5;
    int wn = wid;
    int rbase = m0 + (lane >> 2);
    int cbase = n0 + wn * 32 + (lane & 3) * 2;
#pragma unroll
    for (int mf = 0; mf < 4; mf++)
#pragma unroll
        for (int nf = 0; nf < 4; nf++)
#pragma unroll
            for (int hh2 = 0; hh2 < 2; hh2++) {
                int row = rbase + mf * 16 + hh2 * 8;
                int col = cbase + nf * 8;
                size_t off = ((size_t)b * SS + row) * DD + col;
                float2 iv = *(const float2*)&inputs[off];
                float2 ov;
                ov.x = c[mf][nf][hh2 * 2]     + iv.x;
                ov.y = c[mf][nf][hh2 * 2 + 1] + iv.y;
                *(float2*)&out[off] = ov;
            }
}

// ---------------- scan B: exclusive chunk carries (2 d per thread) -----------------
__global__ void k_scanB() {
    int idx = blockIdx.x * 256 + threadIdx.x;      // over BB*DD/2
    int d2 = idx & (DD / 2 - 1);
    int b = idx >> 9;
    float h0 = 0.0f, h1 = 0.0f;
    for (int c = 0; c < NCH; c++) {
        int off = (b * NCH + c) * DD + d2 * 2;
        float2 A  = *(float2*)&g_cA[off];
        float2 Bc = *(float2*)&g_cB[off];
        *(float2*)&g_cB[off] = make_float2(h0, h1);
        h0 = fmaf(A.x, h0, Bc.x);
        h1 = fmaf(A.y, h1, Bc.y);
    }
}

// ---------------- scan C: apply + h fp16 (2 d per thread) --------------------------
__global__ void k_scanC(const float* __restrict__ state, float* out, int out_size) {
    int idx = blockIdx.x * 256 + threadIdx.x;      // over BB*NCH*DD/2
    int d2 = idx & (DD / 2 - 1);
    int c = (idx >> 9) & (NCH - 1);
    int b = idx >> 15;
    int d = d2 * 2;
    size_t base = (size_t)(b * SS + c * CL) * DD + d;
    float2 hc = *(float2*)&g_cB[(b * NCH + c) * DD + d];
    float h0 = hc.x, h1 = hc.y;
#pragma unroll 8
    for (int s = 0; s < CL; s++) {
        uint2 abp = *(const uint2*)&g_ab[base + (size_t)s * DD];
        __half2 ab0 = *(__half2*)&abp.x;
        __half2 ab1 = *(__half2*)&abp.y;
        float a0 = __low2float(ab0), b0 = __high2float(ab0);
        float a1 = __low2float(ab1), b1 = __high2float(ab1);
        if (c == 0 && s == 0) {
            float2 st = *(const float2*)&state[b * DD + d];
            b0 += a0 * st.x;
            b1 += a1 * st.y;
        }
        h0 = fmaf(a0, h0, b0);
        h1 = fmaf(a1, h1, b1);
        __half2 hv = __floats2half2_rn(h0, h1);
        *(__half2*)&g_hh[base + (size_t)s * DD] = hv;
    }
    if (c == NCH - 1 && out_size >= BB*SS*DD + BB*DD) {
        out[BB*SS*DD + b * DD + d]     = h0;
        out[BB*SS*DD + b * DD + d + 1] = h1;
    }
}

// ---------------- launch ------------------------------------------------------------
extern "C" void kernel_launch(void* const* d_in, const int* in_sizes, int n_in,
                              void* d_out, int out_size) {
    const float* inputs = (const float*)d_in[0];
    const float* state  = (const float*)d_in[1];
    const float* normw  = (const float*)d_in[2];
    const float* rw     = (const float*)d_in[3];
    const float* rb     = (const float*)d_in[4];
    const float* wgh    = (const float*)d_in[5];
    const float* wout   = (const float*)d_in[6];
    float* out = (float*)d_out;

    // one-time host-side setup (host resources only; per-call device work identical)
    static cudaStream_t s2 = nullptr;
    static cudaEvent_t e0, eM;
    if (!s2) {
        cudaStreamCreateWithFlags(&s2, cudaStreamNonBlocking);
        cudaEventCreateWithFlags(&e0, cudaEventDisableTiming);
        cudaEventCreateWithFlags(&eM, cudaEventDisableTiming);
        cudaFuncSetAttribute(k_gemm1, cudaFuncAttributeMaxDynamicSharedMemorySize, SMEM_BYTES);
        cudaFuncSetAttribute(k_gemm2, cudaFuncAttributeMaxDynamicSharedMemorySize, SMEM_BYTES);
    }

    k_rmsnorm<<<dim3(SS / 64, BB), 256>>>(inputs, normw);
    k_router <<<BB, 128>>>(rw, rb, out, out_size);
    cudaEventRecord(e0, 0);

    // s2: mixoT (whole kernel) overlaps gemm1 on the default stream
    cudaStreamWaitEvent(s2, e0, 0);
    k_mixoT<<<dim3(8192, 1), 256, 0, s2>>>(wout);
    cudaEventRecord(eM, s2);

    k_mixgT <<<dim3(8192, 2), 256>>>(wgh);
    k_gemm1 <<<dim3(DD2 / 128, SS / 64, BB), NT, SMEM_BYTES>>>(state);
    k_scanB <<<(BB * DD / 2) / 256, 256>>>();
    k_scanC <<<(BB * NCH * DD / 2) / 256, 256>>>(state, out, out_size);
    cudaStreamWaitEvent(0, eM, 0);
    k_gemm2 <<<dim3(DD / 128, SS / 64, BB), NT, SMEM_BYTES>>>(inputs, out);
}

// round 16
// speedup vs baseline: 1.4849x; 1.0013x over previous
#include <cuda_runtime.h>
#include <cuda_fp16.h>
#include <cstdint>
#include <math.h>

#define BB   8
#define SS   4096
#define DD   1024
#define DD2  2048
#define CL   64
#define NCH  64
#define EPSV 1e-5f

// ---------------- scratch (device globals) -----------------------------------
__device__ __half g_xh[BB*SS*DD];                   // rmsnorm x fp16
__device__ __half g_wg[BB*DD2*DD];                  // mixed Wg^T (interleaved n) fp16
__device__ __half g_wo[BB*DD*DD];                   // mixed Wo^T fp16
__device__ __half g_hh[BB*SS*DD];                   // scan h fp16
__device__ __half2 g_ab[BB*SS*DD];                  // packed gates (a,b) fp16
__device__ float g_part[BB*64*DD];                  // per-block partial colsums
__device__ float g_probs [BB*3];
__device__ float g_cA[BB*NCH*DD], g_cB[BB*NCH*DD];

__device__ __forceinline__ float sigm(float x) { return 1.0f / (1.0f + __expf(-x)); }

__device__ __forceinline__ uint32_t cvta_smem(const void* p) {
    uint32_t a;
    asm("{ .reg .u64 t; cvta.to.shared.u64 t, %1; cvt.u32.u64 %0, t; }" : "=r"(a) : "l"(p));
    return a;
}

// ---------------- portable tensor-core primitives ------------------------------
__device__ __forceinline__ void mma16816(float* c, const uint32_t* a, const uint32_t* b) {
    asm volatile(
        "mma.sync.aligned.m16n8k16.row.col.f32.f16.f16.f32 "
        "{%0,%1,%2,%3},{%4,%5,%6,%7},{%8,%9},{%0,%1,%2,%3};"
        : "+f"(c[0]), "+f"(c[1]), "+f"(c[2]), "+f"(c[3])
        : "r"(a[0]), "r"(a[1]), "r"(a[2]), "r"(a[3]), "r"(b[0]), "r"(b[1]));
}
__device__ __forceinline__ void ldm4(uint32_t* r, uint32_t a) {
    asm volatile("ldmatrix.sync.aligned.m8n8.x4.shared.b16 {%0,%1,%2,%3}, [%4];"
        : "=r"(r[0]), "=r"(r[1]), "=r"(r[2]), "=r"(r[3]) : "r"(a));
}
#define CPA(s, g) asm volatile("cp.async.cg.shared.global [%0], [%1], 16;" :: "r"(s), "l"(g))
#define CP_COMMIT() asm volatile("cp.async.commit_group;")
#define CP_WAIT0()  asm volatile("cp.async.wait_group 0;")

#define NT 128     // threads per GEMM CTA (4 warps); 4 CTAs per SM

// smem stage (BK=64, 128B rows, XOR-swizzled): A 64x128B | B 128x128B ; 2 stages
#define A_BYTES    8192
#define STAGE_B    24576
#define SMEM_BYTES 49152

// swizzled byte offset within a matrix: row r (128B rows), 16B-chunk cc
#define SWZ(r, cc) ((r) * 128 + (((cc) ^ ((r) & 7)) << 4))

template<int ROWS>
__device__ __forceinline__ void load_mat(uint32_t sdst, const __half* g, int tid) {
#pragma unroll
    for (int it = 0; it < ROWS * 8 / NT; it++) {
        int idx = tid + it * NT;
        int r = idx >> 3, cc = idx & 7;
        CPA(sdst + SWZ(r, cc), g + (size_t)r * DD + cc * 8);
    }
}
__device__ __forceinline__ void load_stage(uint32_t sbuf,
    const __half* A, const __half* B, int k0, int tid) {
    load_mat<64> (sbuf,           A + k0, tid);
    load_mat<128>(sbuf + A_BYTES, B + k0, tid);
}

// 64x128 CTA tile, 4 warps (1M x 4N), warp tile 64x32; fp16, BK=64, 2-stage pipe.
__device__ __forceinline__ void gemm_mainloop(
    float c[4][4][4], uint32_t sb,
    const __half* A, const __half* B, int tid) {

    int lane = tid & 31, wid = tid >> 5;
    int wn = wid;                                        // warp grid 1M x 4N
    int ra = lane & 15;                                  // A row (mf adds 16)
    int rb = wn * 32 + (lane & 7) + ((lane >> 4) << 3);  // B row (ng adds 16)
    int ca0 = lane >> 4;                                 // A chunk base (ks adds 2)
    int cb0 = (lane >> 3) & 1;                           // B chunk base (ks adds 2)

    load_stage(sb, A, B, 0, tid); CP_COMMIT();

#pragma unroll 1
    for (int s = 0; s < 16; s++) {
        CP_WAIT0();
        __syncthreads();
        if (s < 15) {
            load_stage(sb + ((s + 1) & 1) * STAGE_B, A, B, (s + 1) * 64, tid);
            CP_COMMIT();
        }
        uint32_t base  = sb + (s & 1) * STAGE_B;
        uint32_t baseB = base + A_BYTES;
#pragma unroll
        for (int ks = 0; ks < 4; ks++) {
            uint32_t ah[4][4], bh[2][4];
#pragma unroll
            for (int mf = 0; mf < 4; mf++)
                ldm4(ah[mf], base + SWZ(ra + mf * 16, ca0 + ks * 2));
#pragma unroll
            for (int ng = 0; ng < 2; ng++)
                ldm4(bh[ng], baseB + SWZ(rb + ng * 16, cb0 + ks * 2));
#pragma unroll
            for (int mf = 0; mf < 4; mf++)
#pragma unroll
                for (int nf = 0; nf < 4; nf++)
                    mma16816(c[mf][nf], ah[mf], &bh[nf >> 1][(nf & 1) * 2]);
        }
    }
    __syncthreads();
}

// ---------------- rmsnorm (float4 vectorized) -> fp16 + partial colsum ------------
__global__ void __launch_bounds__(256) k_rmsnorm(const float* __restrict__ inp,
                                                 const float* __restrict__ normw) {
    int b = blockIdx.y, t = threadIdx.x, warp = t >> 5, lane = t & 31;
    __shared__ float sw[DD];
    __shared__ float scs[DD];
    for (int i = t; i < DD; i += 256) { sw[i] = normw[i]; scs[i] = 0.0f; }
    __syncthreads();

    float csum[8][4];
#pragma unroll
    for (int q = 0; q < 8; q++)
#pragma unroll
        for (int j = 0; j < 4; j++) csum[q][j] = 0.0f;

    int s_base = blockIdx.x * 64;
#pragma unroll 1
    for (int r = 0; r < 8; r++) {
        int s = s_base + warp + r * 8;
        const float4* row4 = (const float4*)(inp + (size_t)(b * SS + s) * DD);
        float4 v[8];
        float ss = 0.0f;
#pragma unroll
        for (int q = 0; q < 8; q++) {
            v[q] = row4[lane + 32 * q];
            ss += v[q].x * v[q].x + v[q].y * v[q].y + v[q].z * v[q].z + v[q].w * v[q].w;
        }
#pragma unroll
        for (int o = 16; o > 0; o >>= 1) ss += __shfl_xor_sync(0xffffffffu, ss, o);
        float inv = rsqrtf(ss * (1.0f / DD) + EPSV);
        uint2* xr = (uint2*)(g_xh + (size_t)(b * SS + s) * DD);
#pragma unroll
        for (int q = 0; q < 8; q++) {
            int col0 = (lane + 32 * q) * 4;
            float x0 = v[q].x * inv * sw[col0 + 0];
            float x1 = v[q].y * inv * sw[col0 + 1];
            float x2 = v[q].z * inv * sw[col0 + 2];
            float x3 = v[q].w * inv * sw[col0 + 3];
            __half2 h01 = __floats2half2_rn(x0, x1);
            __half2 h23 = __floats2half2_rn(x2, x3);
            uint2 pack;
            pack.x = *(uint32_t*)&h01;
            pack.y = *(uint32_t*)&h23;
            xr[lane + 32 * q] = pack;
            csum[q][0] += x0; csum[q][1] += x1; csum[q][2] += x2; csum[q][3] += x3;
        }
    }
#pragma unroll
    for (int q = 0; q < 8; q++) {
        int col0 = (lane + 32 * q) * 4;
#pragma unroll
        for (int j = 0; j < 4; j++) atomicAdd(&scs[col0 + j], csum[q][j]);
    }
    __syncthreads();
    for (int i = t; i < DD; i += 256)
        g_part[((size_t)b * 64 + blockIdx.x) * DD + i] = scs[i];
}

// ---------------- router (reduces partials) + aux_loss ----------------------------
__global__ void k_router(const float* __restrict__ rw, const float* __restrict__ rb,
                         float* out, int out_size) {
    int b = blockIdx.x, t = threadIdx.x;
    if (b == 0 && t == 0 && out_size >= BB*SS*DD + BB*DD + 1)
        out[BB*SS*DD + BB*DD] = 0.0f;
    float p0 = 0, p1 = 0, p2 = 0;
    for (int d = t; d < DD; d += 128) {
        float cs = 0.0f;
        for (int blk = 0; blk < 64; blk++)
            cs += g_part[((size_t)b * 64 + blk) * DD + d];
        cs *= (1.0f / SS);
        p0 += cs * rw[d * 3 + 0];
        p1 += cs * rw[d * 3 + 1];
        p2 += cs * rw[d * 3 + 2];
    }
    __shared__ float sm[3][128];
    sm[0][t] = p0; sm[1][t] = p1; sm[2][t] = p2;
    __syncthreads();
    for (int o = 64; o > 0; o >>= 1) {
        if (t < o) { sm[0][t] += sm[0][t+o]; sm[1][t] += sm[1][t+o]; sm[2][t] += sm[2][t+o]; }
        __syncthreads();
    }
    if (t == 0) {
        float l0 = sm[0][0] + rb[0], l1 = sm[1][0] + rb[1], l2 = sm[2][0] + rb[2];
        float m = fmaxf(l0, fmaxf(l1, l2));
        float e0 = __expf(l0-m), e1 = __expf(l1-m), e2 = __expf(l2-m);
        float inv = 1.0f / (e0 + e1 + e2);
        g_probs[b*3+0] = e0*inv; g_probs[b*3+1] = e1*inv; g_probs[b*3+2] = e2*inv;
    }
}

// ---------------- mix + transpose Wg (interleaved n) -> fp16, float4/uint2 --------
__global__ void __launch_bounds__(256) k_mixgT(const float* __restrict__ wgh) {
    int b = blockIdx.x & 7;
    int tile = blockIdx.x >> 3;
    int which = blockIdx.y;
    int jt = tile & 31, kt2 = tile >> 5;
    int j0 = jt * 32, k0 = kt2 * 32;
    float p0 = g_probs[b*3+0], p1 = g_probs[b*3+1], p2 = g_probs[b*3+2];
    __shared__ float s[32][33];
    int t = threadIdx.x;

    // load: kl = t>>3 (k row), jq = t&7 (float4 group over j); one pass
    {
        int kl = t >> 3, jq = t & 7;
        size_t o0 = (size_t)(k0 + kl) * DD2 + (size_t)which * DD + j0 + jq * 4;
        float4 v0 = *(const float4*)&wgh[o0];
        float4 v1 = *(const float4*)&wgh[o0 + (size_t)DD * DD2];
        float4 v2 = *(const float4*)&wgh[o0 + (size_t)2 * DD * DD2];
        s[kl][jq*4+0] = p0 * v0.x + p1 * v1.x + p2 * v2.x;
        s[kl][jq*4+1] = p0 * v0.y + p1 * v1.y + p2 * v2.y;
        s[kl][jq*4+2] = p0 * v0.z + p1 * v1.z + p2 * v2.z;
        s[kl][jq*4+3] = p0 * v0.w + p1 * v1.w + p2 * v2.w;
    }
    __syncthreads();

    // store: jl = t>>3 (j), kg = t&7 (4 consecutive k) -> uint2 (4 halfs)
    {
        int jl = t >> 3, kg = t & 7;
        __half2 h01 = __floats2half2_rn(s[kg*4+0][jl], s[kg*4+1][jl]);
        __half2 h23 = __floats2half2_rn(s[kg*4+2][jl], s[kg*4+3][jl]);
        uint2 pack;
        pack.x = *(uint32_t*)&h01;
        pack.y = *(uint32_t*)&h23;
        size_t off = ((size_t)b * DD2 + 2*(j0+jl) + which) * DD + k0 + kg * 4;
        *(uint2*)&g_wg[off] = pack;
    }
}

// ---------------- mix + transpose Wo -> fp16, float4/uint2 -------------------------
__global__ void __launch_bounds__(256) k_mixoT(const float* __restrict__ wout) {
    int b = blockIdx.x & 7;
    int tile = blockIdx.x >> 3;
    int jt = tile & 31, kt2 = tile >> 5;
    int j0 = jt * 32, k0 = kt2 * 32;
    float p0 = g_probs[b*3+0], p1 = g_probs[b*3+1], p2 = g_probs[b*3+2];
    __shared__ float s[32][33];
    int t = threadIdx.x;

    {
        int kl = t >> 3, jq = t & 7;
        size_t o0 = (size_t)(k0 + kl) * DD + j0 + jq * 4;
        float4 v0 = *(const float4*)&wout[o0];
        float4 v1 = *(const float4*)&wout[o0 + (size_t)DD * DD];
        float4 v2 = *(const float4*)&wout[o0 + (size_t)2 * DD * DD];
        s[kl][jq*4+0] = p0 * v0.x + p1 * v1.x + p2 * v2.x;
        s[kl][jq*4+1] = p0 * v0.y + p1 * v1.y + p2 * v2.y;
        s[kl][jq*4+2] = p0 * v0.z + p1 * v1.z + p2 * v2.z;
        s[kl][jq*4+3] = p0 * v0.w + p1 * v1.w + p2 * v2.w;
    }
    __syncthreads();

    {
        int jl = t >> 3, kg = t & 7;
        __half2 h01 = __floats2half2_rn(s[kg*4+0][jl], s[kg*4+1][jl]);
        __half2 h23 = __floats2half2_rn(s[kg*4+2][jl], s[kg*4+3][jl]);
        uint2 pack;
        pack.x = *(uint32_t*)&h01;
        pack.y = *(uint32_t*)&h23;
        size_t off = ((size_t)b * DD + j0 + jl) * DD + k0 + kg * 4;
        *(uint2*)&g_wo[off] = pack;
    }
}

// ---------------- GEMM1: hg = x @ Wg^T -> packed (a,b) + fused chunk-scan ---------
__global__ void __launch_bounds__(NT, 4) k_gemm1(const float* __restrict__ state) {
    extern __shared__ __align__(128) char smraw[];
    uint32_t sb = cvta_smem(smraw);
    int tid = threadIdx.x;
    int b = blockIdx.z, m0 = blockIdx.y * 64, n0 = blockIdx.x * 128;

    const __half* A = g_xh + ((size_t)b * SS  + m0) * DD;
    const __half* B = g_wg + ((size_t)b * DD2 + n0) * DD;

    float c[4][4][4];
#pragma unroll
    for (int i = 0; i < 4; i++)
#pragma unroll
        for (int j = 0; j < 4; j++)
#pragma unroll
            for (int k = 0; k < 4; k++) c[i][j][k] = 0.0f;

    gemm_mainloop(c, sb, A, B, tid);

    // stage packed (a,b) half2 into smem (64 rows x 64 j, pitch 68)
    uint32_t* sab = (uint32_t*)smraw;
    int lane = tid & 31, wid = tid >> 5;
    int wn = wid;
    int rloc = lane >> 2;
    int jloc = wn * 16 + (lane & 3);
#pragma unroll
    for (int mf = 0; mf < 4; mf++)
#pragma unroll
        for (int nf = 0; nf < 4; nf++)
#pragma unroll
            for (int hh2 = 0; hh2 < 2; hh2++) {
                float hid  = c[mf][nf][hh2 * 2];
                float gate = c[mf][nf][hh2 * 2 + 1];
                float z  = sigm(gate);
                float gg = (hid >= 0.0f) ? (hid + 0.5f) : sigm(hid);
                int r = rloc + mf * 16 + hh2 * 8;
                int j = jloc + nf * 4;
                __half2 v = __floats2half2_rn(1.0f - z, z * gg);
                sab[r * 68 + j] = *(uint32_t*)&v;
            }
    __syncthreads();

    // coalesced g_ab write (1024 uint4 over 128 threads)
#pragma unroll
    for (int it = 0; it < 8; it++) {
        int idx = tid + it * NT;
        int row = idx >> 4, seg = idx & 15;
        size_t off = ((size_t)b * SS + m0 + row) * DD + (n0 >> 1) + seg * 4;
        uint4 v = *(uint4*)&sab[row * 68 + seg * 4];
        *(uint4*)&g_ab[off] = v;
    }

    // fused scanA: per-chunk (A,B) carries from smem (1 chunk x 64 d-pairs)
    if (tid < 64) {
        int d = tid;
        int cglob = blockIdx.y;                 // chunk index (tile M == CL)
        int dglob = (n0 >> 1) + d;
        float Ac = 1.0f, Bc = 0.0f;
        const uint32_t* base = sab + d;
#pragma unroll 8
        for (int s = 0; s < CL; s++) {
            __half2 ab = *(const __half2*)&base[s * 68];
            float as = __low2float(ab);
            float bs = __high2float(ab);
            if (cglob == 0 && s == 0) bs += as * state[b * DD + dglob];
            Bc = fmaf(as, Bc, bs);
            Ac *= as;
        }
        int off = (b * NCH + cglob) * DD + dglob;
        g_cA[off] = Ac;
        g_cB[off] = Bc;
    }
}

// ---------------- GEMM2: out = h @ Wo^T + inputs ------------------------------------
__global__ void __launch_bounds__(NT, 4) k_gemm2(const float* __restrict__ inputs,
                                                 float* __restrict__ out) {
    extern __shared__ __align__(128) char smraw[];
    uint32_t sb = cvta_smem(smraw);
    int tid = threadIdx.x;
    int b = blockIdx.z, m0 = blockIdx.y * 64, n0 = blockIdx.x * 128;

    const __half* A = g_hh + ((size_t)b * SS + m0) * DD;
    const __half* B = g_wo + ((size_t)b * DD + n0) * DD;

    float c[4][4][4];
#pragma unroll
    for (int i = 0; i < 4; i++)
#pragma unroll
        for (int j = 0; j < 4; j++)
#pragma unroll
            for (int k = 0; k < 4; k++) c[i][j][k] = 0.0f;

    gemm_mainloop(c, sb, A, B, tid);

    int lane = tid & 31, wid = tid >> 5;
    int wn = wid;
    int rbase = m0 + (lane >> 2);
    int cbase = n0 + wn * 32 + (lane & 3) * 2;
#pragma unroll
    for (int mf = 0; mf < 4; mf++)
#pragma unroll
        for (int nf = 0; nf < 4; nf++)
#pragma unroll
            for (int hh2 = 0; hh2 < 2; hh2++) {
                int row = rbase + mf * 16 + hh2 * 8;
                int col = cbase + nf * 8;
                size_t off = ((size_t)b * SS + row) * DD + col;
                float2 iv = *(const float2*)&inputs[off];
                float2 ov;
                ov.x = c[mf][nf][hh2 * 2]     + iv.x;
                ov.y = c[mf][nf][hh2 * 2 + 1] + iv.y;
                *(float2*)&out[off] = ov;
            }
}

// ---------------- scan B: exclusive chunk carries (4 d per thread) -----------------
__global__ void k_scanB() {
    int idx = blockIdx.x * 256 + threadIdx.x;      // over BB*DD/4
    int d4 = idx & (DD / 4 - 1);
    int b = idx >> 8;
    float4 h = make_float4(0.f, 0.f, 0.f, 0.f);
    for (int c = 0; c < NCH; c++) {
        int off = (b * NCH + c) * DD + d4 * 4;
        float4 A  = *(float4*)&g_cA[off];
        float4 Bc = *(float4*)&g_cB[off];
        *(float4*)&g_cB[off] = h;
        h.x = fmaf(A.x, h.x, Bc.x);
        h.y = fmaf(A.y, h.y, Bc.y);
        h.z = fmaf(A.z, h.z, Bc.z);
        h.w = fmaf(A.w, h.w, Bc.w);
    }
}

// ---------------- scan C: apply + h fp16 (4 d per thread) --------------------------
__global__ void k_scanC(const float* __restrict__ state, float* out, int out_size) {
    int idx = blockIdx.x * 256 + threadIdx.x;      // over BB*NCH*DD/4
    int d4 = idx & (DD / 4 - 1);
    int c = (idx >> 8) & (NCH - 1);
    int b = idx >> 14;
    int d = d4 * 4;
    size_t base = (size_t)(b * SS + c * CL) * DD + d;
    float4 hc = *(float4*)&g_cB[(b * NCH + c) * DD + d];
    float h0 = hc.x, h1 = hc.y, h2 = hc.z, h3 = hc.w;
#pragma unroll 8
    for (int s = 0; s < CL; s++) {
        uint4 abp = *(const uint4*)&g_ab[base + (size_t)s * DD];
        __half2 ab0 = *(__half2*)&abp.x;
        __half2 ab1 = *(__half2*)&abp.y;
        __half2 ab2 = *(__half2*)&abp.z;
        __half2 ab3 = *(__half2*)&abp.w;
        float a0 = __low2float(ab0), b0 = __high2float(ab0);
        float a1 = __low2float(ab1), b1 = __high2float(ab1);
        float a2 = __low2float(ab2), b2 = __high2float(ab2);
        float a3 = __low2float(ab3), b3 = __high2float(ab3);
        if (c == 0 && s == 0) {
            float4 st = *(const float4*)&state[b * DD + d];
            b0 += a0 * st.x;
            b1 += a1 * st.y;
            b2 += a2 * st.z;
            b3 += a3 * st.w;
        }
        h0 = fmaf(a0, h0, b0);
        h1 = fmaf(a1, h1, b1);
        h2 = fmaf(a2, h2, b2);
        h3 = fmaf(a3, h3, b3);
        __half2 hv01 = __floats2half2_rn(h0, h1);
        __half2 hv23 = __floats2half2_rn(h2, h3);
        uint2 pack;
        pack.x = *(uint32_t*)&hv01;
        pack.y = *(uint32_t*)&hv23;
        *(uint2*)&g_hh[base + (size_t)s * DD] = pack;
    }
    if (c == NCH - 1 && out_size >= BB*SS*DD + BB*DD) {
        out[BB*SS*DD + b * DD + d]     = h0;
        out[BB*SS*DD + b * DD + d + 1] = h1;
        out[BB*SS*DD + b * DD + d + 2] = h2;
        out[BB*SS*DD + b * DD + d + 3] = h3;
    }
}

// ---------------- launch ------------------------------------------------------------
extern "C" void kernel_launch(void* const* d_in, const int* in_sizes, int n_in,
                              void* d_out, int out_size) {
    const float* inputs = (const float*)d_in[0];
    const float* state  = (const float*)d_in[1];
    const float* normw  = (const float*)d_in[2];
    const float* rw     = (const float*)d_in[3];
    const float* rb     = (const float*)d_in[4];
    const float* wgh    = (const float*)d_in[5];
    const float* wout   = (const float*)d_in[6];
    float* out = (float*)d_out;

    // one-time host-side setup (host resources only; per-call device work identical)
    static cudaStream_t s2 = nullptr;
    static cudaEvent_t e0, eM;
    if (!s2) {
        cudaStreamCreateWithFlags(&s2, cudaStreamNonBlocking);
        cudaEventCreateWithFlags(&e0, cudaEventDisableTiming);
        cudaEventCreateWithFlags(&eM, cudaEventDisableTiming);
        cudaFuncSetAttribute(k_gemm1, cudaFuncAttributeMaxDynamicSharedMemorySize, SMEM_BYTES);
        cudaFuncSetAttribute(k_gemm2, cudaFuncAttributeMaxDynamicSharedMemorySize, SMEM_BYTES);
    }

    k_rmsnorm<<<dim3(SS / 64, BB), 256>>>(inputs, normw);
    k_router <<<BB, 128>>>(rw, rb, out, out_size);
    cudaEventRecord(e0, 0);

    // s2: mixoT (whole kernel) overlaps gemm1 on the default stream
    cudaStreamWaitEvent(s2, e0, 0);
    k_mixoT<<<dim3(8192, 1), 256, 0, s2>>>(wout);
    cudaEventRecord(eM, s2);

    k_mixgT <<<dim3(8192, 2), 256>>>(wgh);
    k_gemm1 <<<dim3(DD2 / 128, SS / 64, BB), NT, SMEM_BYTES>>>(state);
    k_scanB <<<(BB * DD / 4) / 256, 256>>>();
    k_scanC <<<(BB * NCH * DD / 4) / 256, 256>>>(state, out, out_size);
    cudaStreamWaitEvent(0, eM, 0);
    k_gemm2 <<<dim3(DD / 128, SS / 64, BB), NT, SMEM_BYTES>>>(inputs, out);
}